// round 4
// baseline (speedup 1.0000x reference)
#include <cuda_runtime.h>
#include <math.h>

// ---------------------------------------------------------------------------
// Problem constants
// ---------------------------------------------------------------------------
#define B 2048
#define C1 15
#define C2 30
#define P1 29                       // pooled size after conv1
#define P2 11                       // pooled size after conv2
#define IN2 29                      // conv2 input spatial
#define IN2P 32                     // padded row stride for conv2 input
#define FC1_IN (30*11*11)           // 3630
#define FC1_OUT 200
#define KSPLIT 11                   // fc1 K-split factor

typedef unsigned long long ull;

// ---------------------------------------------------------------------------
// Packed f32x2 helpers (sm_103a): one FFMA2 = two independent fp32 FMAs.
// ---------------------------------------------------------------------------
__device__ __forceinline__ ull pack_dup(float v) {
    ull r; unsigned int u = __float_as_uint(v);
    asm("mov.b64 %0, {%1, %2};" : "=l"(r) : "r"(u), "r"(u));
    return r;
}
__device__ __forceinline__ void ffma2(ull& d, ull a, ull b) {
    asm("fma.rn.f32x2 %0, %1, %2, %3;" : "=l"(d) : "l"(a), "l"(b), "l"(d));
}
__device__ __forceinline__ float2 unpack2(ull p) {
    unsigned int lo, hi;
    asm("mov.b64 {%0, %1}, %2;" : "=r"(lo), "=r"(hi) : "l"(p));
    return make_float2(__uint_as_float(lo), __uint_as_float(hi));
}

// ---------------------------------------------------------------------------
// Scratch (static __device__ — no allocation allowed)
// ---------------------------------------------------------------------------
__device__ float g_p1[B * C1 * P1 * IN2P];           // padded [b][c][29][32]
__device__ float g_p2[B * C2 * P2 * P2];             // [b][c][11][11]
__device__ float g_fc1p[KSPLIT * B * FC1_OUT];       // fc1 K-partials

// ---------------------------------------------------------------------------
// Kernel 1: PCEN + conv1 (1->16ch padded, 7x7) + BN + ReLU + 2x2 maxpool.
// One block per image, 288 threads. Conv math in packed f32x2 over channel
// pairs: weight pair {w[c], w[c+1]} is one ld.shared.b64.
// ---------------------------------------------------------------------------
__global__ __launch_bounds__(288) void conv1_pcen_kernel(
    const float* __restrict__ x,
    const float* __restrict__ log_s, const float* __restrict__ log_alpha,
    const float* __restrict__ log_delta, const float* __restrict__ log_r,
    const float* __restrict__ w1, const float* __restrict__ b1,
    const float* __restrict__ g,  const float* __restrict__ be,
    const float* __restrict__ mu, const float* __restrict__ va)
{
    __shared__ __align__(16) float inS[64 * 66];
    __shared__ __align__(16) float wT[49 * 16];      // [k][c16], c15 = 0
    __shared__ float scS[C1], shS[C1];

    const int b = blockIdx.x, t = threadIdx.x;
    const float* xb = x + (size_t)b * 4096;

    for (int i = t; i < 4096; i += 288)
        inS[(i >> 6) * 66 + (i & 63)] = xb[i];
    for (int i = t; i < 49 * 16; i += 288) {
        int k = i >> 4, c = i & 15;
        wT[i] = (c < C1) ? w1[c * 49 + k] : 0.f;
    }
    if (t < C1) {
        float inv = g[t] * rsqrtf(va[t] + 1e-5f);
        scS[t] = inv;
        shS[t] = (b1[t] - mu[t]) * inv + be[t];
    }
    __syncthreads();

    // PCEN recurrence: thread t < 64 owns row h = t, loop over w
    if (t < 64) {
        const float s     = expf(log_s[0]);
        const float alpha = expf(log_alpha[0]);
        const float delta = expf(log_delta[0]);
        const float r     = expf(log_r[0]);
        const float oms   = 1.0f - s;
        const float dr    = powf(delta, r);
        float* row = inS + t * 66;
        float m = 0.0f;
        #pragma unroll 4
        for (int w = 0; w < 64; w++) {
            float xv = row[w];
            m = (w == 0) ? s * xv : oms * m + s * xv;
            float Ma = __powf(m + 1e-6f, alpha);
            row[w] = __powf(__fdividef(xv, Ma) + delta, r) - dr;
        }
    }
    __syncthreads();

    for (int pos = t; pos < P1 * P1; pos += 288) {
        const int pi = pos / P1, pj = pos % P1;
        ull acc[8][4];
        #pragma unroll
        for (int q = 0; q < 8; q++)
            { acc[q][0]=0ull; acc[q][1]=0ull; acc[q][2]=0ull; acc[q][3]=0ull; }
        const float* ip = inS + (2 * pi) * 66 + 2 * pj;   // even offset

        #pragma unroll 1
        for (int dy = 0; dy < 7; dy++) {
            float rA[8], rB[8];
            const float* r0 = ip + dy * 66;
            #pragma unroll
            for (int k = 0; k < 4; k++) {
                float2 a = *(const float2*)&r0[2 * k];
                float2 bq = *(const float2*)&r0[66 + 2 * k];
                rA[2 * k] = a.x;  rA[2 * k + 1] = a.y;
                rB[2 * k] = bq.x; rB[2 * k + 1] = bq.y;
            }
            ull dA[8], dB[8];
            #pragma unroll
            for (int k = 0; k < 8; k++) { dA[k] = pack_dup(rA[k]); dB[k] = pack_dup(rB[k]); }
            #pragma unroll
            for (int dx = 0; dx < 7; dx++) {
                const ull* wq = (const ull*)(wT + (dy * 7 + dx) * 16);
                #pragma unroll
                for (int q = 0; q < 8; q++) {
                    ull w = wq[q];
                    ffma2(acc[q][0], dA[dx],     w);
                    ffma2(acc[q][1], dA[dx + 1], w);
                    ffma2(acc[q][2], dB[dx],     w);
                    ffma2(acc[q][3], dB[dx + 1], w);
                }
            }
        }
        float* ob = g_p1 + (size_t)b * (C1 * P1 * IN2P) + pi * IN2P + pj;
        #pragma unroll
        for (int q = 0; q < 8; q++) {
            float2 v0 = unpack2(acc[q][0]);
            float2 v1 = unpack2(acc[q][1]);
            float2 v2 = unpack2(acc[q][2]);
            float2 v3 = unpack2(acc[q][3]);
            const int c0 = 2 * q, c1 = 2 * q + 1;
            {
                float sc = scS[c0], sh = shS[c0];
                float a0 = fmaxf(v0.x * sc + sh, 0.f);
                float a1 = fmaxf(v1.x * sc + sh, 0.f);
                float a2 = fmaxf(v2.x * sc + sh, 0.f);
                float a3 = fmaxf(v3.x * sc + sh, 0.f);
                ob[c0 * (P1 * IN2P)] = fmaxf(fmaxf(a0, a1), fmaxf(a2, a3));
            }
            if (c1 < C1) {
                float sc = scS[c1], sh = shS[c1];
                float a0 = fmaxf(v0.y * sc + sh, 0.f);
                float a1 = fmaxf(v1.y * sc + sh, 0.f);
                float a2 = fmaxf(v2.y * sc + sh, 0.f);
                float a3 = fmaxf(v3.y * sc + sh, 0.f);
                ob[c1 * (P1 * IN2P)] = fmaxf(fmaxf(a0, a1), fmaxf(a2, a3));
            }
        }
    }
}

// ---------------------------------------------------------------------------
// Kernel 2: conv2 (15->30, 7x7) + BN + ReLU + 2x2 maxpool, packed f32x2.
// One block per image, 384 threads. Thread = 1 pooled pixel x 10 output
// channels = 5 channel-pairs x 4 positions of packed accumulators.
// ---------------------------------------------------------------------------
#define C2_IN_FLOATS  (C1 * P1 * IN2P)                 // 13920
#define C2_W_FLOATS   (C2 * C1 * 49)                   // 22050
#define C2_SMEM_FLOATS (C2_IN_FLOATS + C2_W_FLOATS + 2 * C2)
__global__ __launch_bounds__(384) void conv2_kernel(
    const float* __restrict__ w2, const float* __restrict__ b2,
    const float* __restrict__ g,  const float* __restrict__ be,
    const float* __restrict__ mu, const float* __restrict__ va)
{
    extern __shared__ __align__(16) float sm[];
    float* inS = sm;                       // 13920
    float* wT  = sm + C2_IN_FLOATS;        // 22050: [ic*49+k][oc]
    float* scS = wT + C2_W_FLOATS;
    float* shS = scS + C2;

    const int t = threadIdx.x;
    const int b = blockIdx.x;

    {
        const float4* s4 = (const float4*)(g_p1 + (size_t)b * C2_IN_FLOATS);
        float4* d4 = (float4*)inS;
        for (int i = t; i < C2_IN_FLOATS / 4; i += 384) d4[i] = s4[i];
    }
    for (int i = t; i < C2_W_FLOATS; i += 384) {
        int oc = i / 735, rem = i % 735;
        wT[rem * 30 + oc] = w2[i];
    }
    if (t < C2) {
        float inv = g[t] * rsqrtf(va[t] + 1e-5f);
        scS[t] = inv;
        shS[t] = (b2[t] - mu[t]) * inv + be[t];
    }
    __syncthreads();

    const int item = t;                     // 363 items: 3 grp x 121 pos
    if (item < 363) {
        const int pos = item % 121;
        const int grp = item / 121;
        const int pi = pos / P2, pj = pos % P2;

        ull acc[5][4];
        #pragma unroll
        for (int q = 0; q < 5; q++)
            { acc[q][0]=0ull; acc[q][1]=0ull; acc[q][2]=0ull; acc[q][3]=0ull; }
        const float* ipb = inS + (2 * pi) * IN2P + 2 * pj;   // even offset
        const int ocBase = grp * 10;                          // even -> 8B aligned

        #pragma unroll 1
        for (int ic = 0; ic < C1; ic++) {
            const float* ip = ipb + ic * (P1 * IN2P);
            const float* wc = wT + (ic * 49) * 30 + ocBase;
            #pragma unroll 1
            for (int dy = 0; dy < 7; dy++) {
                float rA[8], rB[8];
                const float* r0 = ip + dy * IN2P;
                #pragma unroll
                for (int k = 0; k < 4; k++) {
                    float2 a = *(const float2*)&r0[2 * k];
                    float2 bq = *(const float2*)&r0[IN2P + 2 * k];
                    rA[2 * k] = a.x;  rA[2 * k + 1] = a.y;
                    rB[2 * k] = bq.x; rB[2 * k + 1] = bq.y;
                }
                ull dA[8], dB[8];
                #pragma unroll
                for (int k = 0; k < 8; k++) { dA[k] = pack_dup(rA[k]); dB[k] = pack_dup(rB[k]); }
                #pragma unroll
                for (int dx = 0; dx < 7; dx++) {
                    const ull* wq = (const ull*)(wc + (dy * 7 + dx) * 30);
                    #pragma unroll
                    for (int q = 0; q < 5; q++) {
                        ull w = wq[q];
                        ffma2(acc[q][0], dA[dx],     w);
                        ffma2(acc[q][1], dA[dx + 1], w);
                        ffma2(acc[q][2], dB[dx],     w);
                        ffma2(acc[q][3], dB[dx + 1], w);
                    }
                }
            }
        }
        #pragma unroll
        for (int q = 0; q < 5; q++) {
            float2 v0 = unpack2(acc[q][0]);
            float2 v1 = unpack2(acc[q][1]);
            float2 v2 = unpack2(acc[q][2]);
            float2 v3 = unpack2(acc[q][3]);
            const int c0 = ocBase + 2 * q, c1 = c0 + 1;
            {
                float sc = scS[c0], sh = shS[c0];
                float a0 = fmaxf(v0.x * sc + sh, 0.f);
                float a1 = fmaxf(v1.x * sc + sh, 0.f);
                float a2 = fmaxf(v2.x * sc + sh, 0.f);
                float a3 = fmaxf(v3.x * sc + sh, 0.f);
                g_p2[(((size_t)b * C2 + c0) * P2 + pi) * P2 + pj] =
                    fmaxf(fmaxf(a0, a1), fmaxf(a2, a3));
            }
            {
                float sc = scS[c1], sh = shS[c1];
                float a0 = fmaxf(v0.y * sc + sh, 0.f);
                float a1 = fmaxf(v1.y * sc + sh, 0.f);
                float a2 = fmaxf(v2.y * sc + sh, 0.f);
                float a3 = fmaxf(v3.y * sc + sh, 0.f);
                g_p2[(((size_t)b * C2 + c1) * P2 + pi) * P2 + pj] =
                    fmaxf(fmaxf(a0, a1), fmaxf(a2, a3));
            }
        }
    }
}

// ---------------------------------------------------------------------------
// Kernel 3: FC1 partial GEMM with K-split (deterministic, no atomics).
// ---------------------------------------------------------------------------
#define KC 30
__global__ __launch_bounds__(128) void fc1_kernel(
    const float* __restrict__ w)
{
    __shared__ __align__(16) float As[KC * 32];
    __shared__ __align__(16) float Bs[KC * 128];
    const int t = threadIdx.x;
    const int mt = blockIdx.x;      // 0..63
    const int nt = blockIdx.y;      // 0..1
    const int kz = blockIdx.z;      // 0..10
    const int tx = t & 31, ty = t >> 5;

    float acc[8][4];
    #pragma unroll
    for (int i = 0; i < 8; i++)
        { acc[i][0]=0.f; acc[i][1]=0.f; acc[i][2]=0.f; acc[i][3]=0.f; }

    const float* act = g_p2 + (size_t)mt * 32 * FC1_IN;
    const int kc0 = kz * 11;

    for (int kc = kc0; kc < kc0 + 11; kc++) {
        for (int i = t; i < KC * 32; i += 128) {
            int bb = i / KC, k = i % KC;
            As[k * 32 + bb] = act[bb * FC1_IN + kc * KC + k];
        }
        for (int i = t; i < KC * 128; i += 128) {
            int o = i / KC, k = i % KC;
            int go = nt * 128 + o;
            Bs[k * 128 + o] = (go < FC1_OUT) ? w[(size_t)go * FC1_IN + kc * KC + k] : 0.f;
        }
        __syncthreads();
        #pragma unroll 1
        for (int k = 0; k < KC; k++) {
            float4 bv = *(const float4*)&Bs[k * 128 + tx * 4];
            float4 a0 = *(const float4*)&As[k * 32 + ty * 8];
            float4 a1 = *(const float4*)&As[k * 32 + ty * 8 + 4];
            const float av[8] = {a0.x, a0.y, a0.z, a0.w, a1.x, a1.y, a1.z, a1.w};
            #pragma unroll
            for (int i = 0; i < 8; i++) {
                acc[i][0] += av[i] * bv.x;
                acc[i][1] += av[i] * bv.y;
                acc[i][2] += av[i] * bv.z;
                acc[i][3] += av[i] * bv.w;
            }
        }
        __syncthreads();
    }
    float* dst = g_fc1p + (size_t)kz * B * FC1_OUT;
    #pragma unroll
    for (int i = 0; i < 8; i++) {
        const int bb = mt * 32 + ty * 8 + i;
        #pragma unroll
        for (int j = 0; j < 4; j++) {
            int o = nt * 128 + tx * 4 + j;
            if (o < FC1_OUT)
                dst[(size_t)bb * FC1_OUT + o] = acc[i][j];
        }
    }
}

// ---------------------------------------------------------------------------
// Kernel 4: sum K-partials + bias + ReLU, then FC2 (200 -> 2) + sigmoid.
// ---------------------------------------------------------------------------
__global__ __launch_bounds__(256) void fc2_kernel(
    const float* __restrict__ fc1b,
    const float* __restrict__ w2, const float* __restrict__ b2,
    float* __restrict__ out)
{
    const int warp = threadIdx.x >> 5, lane = threadIdx.x & 31;
    const int b = blockIdx.x * 8 + warp;
    const size_t PS = (size_t)B * FC1_OUT;
    const float* base = g_fc1p + (size_t)b * FC1_OUT;
    float s0 = 0.f, s1 = 0.f;
    for (int o = lane; o < FC1_OUT; o += 32) {
        float v = fc1b[o];
        #pragma unroll
        for (int p = 0; p < KSPLIT; p++)
            v += base[p * PS + o];
        v = fmaxf(v, 0.f);
        s0 += v * w2[o];
        s1 += v * w2[FC1_OUT + o];
    }
    #pragma unroll
    for (int d = 16; d > 0; d >>= 1) {
        s0 += __shfl_xor_sync(0xFFFFFFFFu, s0, d);
        s1 += __shfl_xor_sync(0xFFFFFFFFu, s1, d);
    }
    if (lane == 0) {
        out[2 * b + 0] = 1.f / (1.f + expf(-(s0 + b2[0])));
        out[2 * b + 1] = 1.f / (1.f + expf(-(s1 + b2[1])));
    }
}

// ---------------------------------------------------------------------------
// Launch
// ---------------------------------------------------------------------------
extern "C" void kernel_launch(void* const* d_in, const int* in_sizes, int n_in,
                              void* d_out, int out_size)
{
    const float* x       = (const float*)d_in[0];
    const float* log_s   = (const float*)d_in[1];
    const float* log_a   = (const float*)d_in[2];
    const float* log_d   = (const float*)d_in[3];
    const float* log_r   = (const float*)d_in[4];
    const float* conv1_w = (const float*)d_in[5];
    const float* conv1_b = (const float*)d_in[6];
    const float* bn1_g   = (const float*)d_in[7];
    const float* bn1_b   = (const float*)d_in[8];
    const float* bn1_m   = (const float*)d_in[9];
    const float* bn1_v   = (const float*)d_in[10];
    const float* conv2_w = (const float*)d_in[11];
    const float* conv2_b = (const float*)d_in[12];
    const float* bn2_g   = (const float*)d_in[13];
    const float* bn2_b   = (const float*)d_in[14];
    const float* bn2_m   = (const float*)d_in[15];
    const float* bn2_v   = (const float*)d_in[16];
    const float* fc1_w   = (const float*)d_in[17];
    const float* fc1_b   = (const float*)d_in[18];
    const float* fc2_w   = (const float*)d_in[19];
    const float* fc2_b   = (const float*)d_in[20];
    float* out = (float*)d_out;

    conv1_pcen_kernel<<<B, 288>>>(x, log_s, log_a, log_d, log_r,
                                  conv1_w, conv1_b, bn1_g, bn1_b, bn1_m, bn1_v);

    static int smem_set = 0;
    const int smem2 = C2_SMEM_FLOATS * sizeof(float);   // ~141 KB
    if (!smem_set) {
        cudaFuncSetAttribute(conv2_kernel,
                             cudaFuncAttributeMaxDynamicSharedMemorySize, smem2);
        smem_set = 1;
    }
    conv2_kernel<<<B, 384, smem2>>>(conv2_w, conv2_b, bn2_g, bn2_b, bn2_m, bn2_v);

    fc1_kernel<<<dim3(64, 2, KSPLIT), 128>>>(fc1_w);
    fc2_kernel<<<B / 8, 256>>>(fc1_b, fc2_w, fc2_b, out);
}

// round 6
// speedup vs baseline: 1.0370x; 1.0370x over previous
#include <cuda_runtime.h>
#include <cuda_bf16.h>
#include <math.h>
#include <stdint.h>

#define B 2048
#define C1 15
#define C2 30
#define P1 29
#define P2 11
#define IN2P 32
#define FC1_IN (30*11*11)
#define FC1_OUT 200
#define KSPLIT 11

typedef unsigned long long ull;
typedef __nv_bfloat16 bf16;

// ---------------- f32x2 helpers (conv1) ----------------
__device__ __forceinline__ ull pack_dup(float v) {
    ull r; unsigned int u = __float_as_uint(v);
    asm("mov.b64 %0, {%1, %2};" : "=l"(r) : "r"(u), "r"(u));
    return r;
}
__device__ __forceinline__ void ffma2(ull& d, ull a, ull b) {
    asm("fma.rn.f32x2 %0, %1, %2, %3;" : "=l"(d) : "l"(a), "l"(b), "l"(d));
}
__device__ __forceinline__ float2 unpack2(ull p) {
    unsigned int lo, hi;
    asm("mov.b64 {%0, %1}, %2;" : "=r"(lo), "=r"(hi) : "l"(p));
    return make_float2(__uint_as_float(lo), __uint_as_float(hi));
}

// ---------------- warp mma m16n8k8 tf32 ----------------
__device__ __forceinline__ void mma_tf32(float* d, uint32_t a0, uint32_t a1,
                                         uint32_t a2, uint32_t a3,
                                         uint32_t b0, uint32_t b1) {
    asm volatile(
        "mma.sync.aligned.m16n8k8.row.col.f32.tf32.tf32.f32 "
        "{%0,%1,%2,%3}, {%4,%5,%6,%7}, {%8,%9}, {%0,%1,%2,%3};"
        : "+f"(d[0]), "+f"(d[1]), "+f"(d[2]), "+f"(d[3])
        : "r"(a0), "r"(a1), "r"(a2), "r"(a3), "r"(b0), "r"(b1));
}

// ---------------- scratch ----------------
__device__ float g_p1[B * C1 * P1 * IN2P];
__device__ float g_p2[B * C2 * P2 * P2];
__device__ float g_fc1p[KSPLIT * B * FC1_OUT];
__device__ uint32_t g_Bfrag[105 * 256];   // [kstep][nt(4)][lane(32)][hi,lo] bf16x2

// ---------------- kernel 0: prep conv2 B fragments ----------------
__global__ void prep_b_frag(const float* __restrict__ w2)
{
    int idx = blockIdx.x * 256 + threadIdx.x;
    if (idx >= 13440) return;
    int ks = idx / 128, r = idx % 128, nt = r / 32, lane = r % 32;
    int ic = ks / 7, dy = ks % 7;
    int oc = nt * 8 + (lane >> 2), k0 = lane & 3;
    const float* wb = w2 + ((oc * C1 + ic) * 7 + dy) * 7;
    float v0 = (oc < C2) ? wb[k0] : 0.f;
    float v1 = (oc < C2 && k0 + 4 < 7) ? wb[k0 + 4] : 0.f;
    uint32_t h0 = (uint32_t)__bfloat16_as_ushort(__float2bfloat16(v0));
    uint32_t h1 = (uint32_t)__bfloat16_as_ushort(__float2bfloat16(v1));
    float l0 = v0 - __uint_as_float(h0 << 16);
    float l1 = v1 - __uint_as_float(h1 << 16);
    uint32_t g0 = (uint32_t)__bfloat16_as_ushort(__float2bfloat16(l0));
    uint32_t g1 = (uint32_t)__bfloat16_as_ushort(__float2bfloat16(l1));
    g_Bfrag[ks * 256 + nt * 64 + lane * 2]     = h0 | (h1 << 16);
    g_Bfrag[ks * 256 + nt * 64 + lane * 2 + 1] = g0 | (g1 << 16);
}

// ---------------- kernel 1: PCEN + conv1 + BN + ReLU + pool ----------------
__global__ __launch_bounds__(288) void conv1_pcen_kernel(
    const float* __restrict__ x,
    const float* __restrict__ log_s, const float* __restrict__ log_alpha,
    const float* __restrict__ log_delta, const float* __restrict__ log_r,
    const float* __restrict__ w1, const float* __restrict__ b1,
    const float* __restrict__ g,  const float* __restrict__ be,
    const float* __restrict__ mu, const float* __restrict__ va)
{
    __shared__ __align__(16) float inS[64 * 66];
    __shared__ __align__(16) float wT[49 * 16];
    __shared__ float scS[C1], shS[C1];

    const int b = blockIdx.x, t = threadIdx.x;
    const float* xb = x + (size_t)b * 4096;

    for (int i = t; i < 4096; i += 288)
        inS[(i >> 6) * 66 + (i & 63)] = xb[i];
    for (int i = t; i < 49 * 16; i += 288) {
        int k = i >> 4, c = i & 15;
        wT[i] = (c < C1) ? w1[c * 49 + k] : 0.f;
    }
    if (t < C1) {
        float inv = g[t] * rsqrtf(va[t] + 1e-5f);
        scS[t] = inv;
        shS[t] = (b1[t] - mu[t]) * inv + be[t];
    }
    __syncthreads();

    if (t < 64) {
        const float s     = expf(log_s[0]);
        const float alpha = expf(log_alpha[0]);
        const float delta = expf(log_delta[0]);
        const float r     = expf(log_r[0]);
        const float oms   = 1.0f - s;
        const float dr    = powf(delta, r);
        float* row = inS + t * 66;
        float m = 0.0f;
        #pragma unroll 4
        for (int w = 0; w < 64; w++) {
            float xv = row[w];
            m = (w == 0) ? s * xv : oms * m + s * xv;
            float Ma = __powf(m + 1e-6f, alpha);
            row[w] = __powf(__fdividef(xv, Ma) + delta, r) - dr;
        }
    }
    __syncthreads();

    for (int pos = t; pos < P1 * P1; pos += 288) {
        const int pi = pos / P1, pj = pos % P1;
        ull acc[8][4];
        #pragma unroll
        for (int q = 0; q < 8; q++)
            { acc[q][0]=0ull; acc[q][1]=0ull; acc[q][2]=0ull; acc[q][3]=0ull; }
        const float* ip = inS + (2 * pi) * 66 + 2 * pj;

        #pragma unroll 1
        for (int dy = 0; dy < 7; dy++) {
            float rA[8], rB[8];
            const float* r0 = ip + dy * 66;
            #pragma unroll
            for (int k = 0; k < 4; k++) {
                float2 a = *(const float2*)&r0[2 * k];
                float2 bq = *(const float2*)&r0[66 + 2 * k];
                rA[2 * k] = a.x;  rA[2 * k + 1] = a.y;
                rB[2 * k] = bq.x; rB[2 * k + 1] = bq.y;
            }
            ull dA[8], dB[8];
            #pragma unroll
            for (int k = 0; k < 8; k++) { dA[k] = pack_dup(rA[k]); dB[k] = pack_dup(rB[k]); }
            #pragma unroll
            for (int dx = 0; dx < 7; dx++) {
                const ull* wq = (const ull*)(wT + (dy * 7 + dx) * 16);
                #pragma unroll
                for (int q = 0; q < 8; q++) {
                    ull w = wq[q];
                    ffma2(acc[q][0], dA[dx],     w);
                    ffma2(acc[q][1], dA[dx + 1], w);
                    ffma2(acc[q][2], dB[dx],     w);
                    ffma2(acc[q][3], dB[dx + 1], w);
                }
            }
        }
        float* ob = g_p1 + (size_t)b * (C1 * P1 * IN2P) + pi * IN2P + pj;
        #pragma unroll
        for (int q = 0; q < 8; q++) {
            float2 v0 = unpack2(acc[q][0]);
            float2 v1 = unpack2(acc[q][1]);
            float2 v2 = unpack2(acc[q][2]);
            float2 v3 = unpack2(acc[q][3]);
            const int c0 = 2 * q, c1 = 2 * q + 1;
            {
                float sc = scS[c0], sh = shS[c0];
                float a0 = fmaxf(v0.x * sc + sh, 0.f);
                float a1 = fmaxf(v1.x * sc + sh, 0.f);
                float a2 = fmaxf(v2.x * sc + sh, 0.f);
                float a3 = fmaxf(v3.x * sc + sh, 0.f);
                ob[c0 * (P1 * IN2P)] = fmaxf(fmaxf(a0, a1), fmaxf(a2, a3));
            }
            if (c1 < C1) {
                float sc = scS[c1], sh = shS[c1];
                float a0 = fmaxf(v0.y * sc + sh, 0.f);
                float a1 = fmaxf(v1.y * sc + sh, 0.f);
                float a2 = fmaxf(v2.y * sc + sh, 0.f);
                float a3 = fmaxf(v3.y * sc + sh, 0.f);
                ob[c1 * (P1 * IN2P)] = fmaxf(fmaxf(a0, a1), fmaxf(a2, a3));
            }
        }
    }
}

// ---------------- kernel 2: conv2 via warp mma (tf32, 3-term split) ----------------
// smem: hi plane 55680 | lo plane 55680 | B frags 107520 (stage reuses) | BN
#define SM_PH 0
#define SM_PL 55680
#define SM_BF 111360
#define SM_SC 218880
#define SM_SH 219008
#define SM_TOT 219264

__global__ __launch_bounds__(256, 1) void conv2_mma_kernel(
    const float* __restrict__ b2,
    const float* __restrict__ g,  const float* __restrict__ be,
    const float* __restrict__ mu, const float* __restrict__ va)
{
    extern __shared__ __align__(16) char smem[];
    uint32_t* pH = (uint32_t*)(smem + SM_PH);
    uint32_t* pL = (uint32_t*)(smem + SM_PL);
    uint32_t* bS = (uint32_t*)(smem + SM_BF);
    float* scS = (float*)(smem + SM_SC);
    float* shS = (float*)(smem + SM_SH);

    const int t = threadIdx.x, w = t >> 5, lane = t & 31;
    const int b = blockIdx.x;

    // build hi/lo planes (hi = bf16-valued f32, lo = tf32-rounded residual)
    {
        const float* src = g_p1 + (size_t)b * 13920;
        for (int i = t; i < 13920; i += 256) {
            float v = src[i];
            uint32_t hb = ((uint32_t)__bfloat16_as_ushort(__float2bfloat16(v))) << 16;
            float lo = v - __uint_as_float(hb);
            uint32_t lb;
            asm("cvt.rna.tf32.f32 %0, %1;" : "=r"(lb) : "f"(lo));
            pH[i] = hb;
            pL[i] = lb;
        }
    }
    // B fragments
    for (int i = t; i < 105 * 256; i += 256) bS[i] = g_Bfrag[i];
    if (t < C2) {
        float inv = g[t] * rsqrtf(va[t] + 1e-5f);
        scS[t] = inv;
        shS[t] = (b2[t] - mu[t]) * inv + be[t];
    }
    __syncthreads();

    // per-warp mtiles: mt = min(w*4+i, 30); A row offsets per mtile
    int o0[4], o1[4];
    #pragma unroll
    for (int i = 0; i < 4; i++) {
        int mt = w * 4 + i; if (mt > 30) mt = 30;
        int p0 = mt * 16 + (lane >> 2); if (p0 > 483) p0 = 483;
        int p1 = p0 + 8;                if (p1 > 483) p1 = 483;
        int y0 = p0 / 22, x0 = p0 - y0 * 22;
        int y1 = p1 / 22, x1 = p1 - y1 * 22;
        o0[i] = y0 * 32 + x0 + (lane & 3);
        o1[i] = y1 * 32 + x1 + (lane & 3);
    }

    float acc[4][4][4];
    #pragma unroll
    for (int i = 0; i < 4; i++)
        #pragma unroll
        for (int n = 0; n < 4; n++)
            { acc[i][n][0]=0.f; acc[i][n][1]=0.f; acc[i][n][2]=0.f; acc[i][n][3]=0.f; }

    #pragma unroll 1
    for (int ic = 0; ic < 15; ic++) {
        #pragma unroll 1
        for (int dy = 0; dy < 7; dy++) {
            const int kb = (ic * 29 + dy) * 32;
            const int ks = ic * 7 + dy;
            // B fragments for this kstep (hi/lo bf16 pairs -> f32 via shifts)
            uint32_t bh[4][2], bl[4][2];
            #pragma unroll
            for (int n = 0; n < 4; n++) {
                uint2 q = *(const uint2*)&bS[ks * 256 + n * 64 + lane * 2];
                bh[n][0] = q.x << 16;  bh[n][1] = q.x & 0xFFFF0000u;
                bl[n][0] = q.y << 16;  bl[n][1] = q.y & 0xFFFF0000u;
            }
            #pragma unroll
            for (int i = 0; i < 4; i++) {
                uint32_t ah0 = pH[kb + o0[i]],     ah2 = pH[kb + o0[i] + 4];
                uint32_t ah1 = pH[kb + o1[i]],     ah3 = pH[kb + o1[i] + 4];
                uint32_t al0 = pL[kb + o0[i]],     al2 = pL[kb + o0[i] + 4];
                uint32_t al1 = pL[kb + o1[i]],     al3 = pL[kb + o1[i] + 4];
                #pragma unroll
                for (int n = 0; n < 4; n++) {
                    mma_tf32(acc[i][n], ah0, ah1, ah2, ah3, bh[n][0], bh[n][1]);
                    mma_tf32(acc[i][n], ah0, ah1, ah2, ah3, bl[n][0], bl[n][1]);
                    mma_tf32(acc[i][n], al0, al1, al2, al3, bh[n][0], bh[n][1]);
                }
            }
        }
    }

    __syncthreads();             // B region now reusable as stage
    float* stg = (float*)(smem + SM_BF);   // [pos 484][33]
    #pragma unroll
    for (int i = 0; i < 4; i++) {
        int mt = w * 4 + i; if (mt > 30) mt = 30;
        int r0 = mt * 16 + (lane >> 2), r1 = r0 + 8;
        #pragma unroll
        for (int n = 0; n < 4; n++) {
            int oc = n * 8 + (lane & 3) * 2;
            if (oc < C2) {
                float s0 = scS[oc], h0 = shS[oc];
                float s1 = scS[oc + 1], h1 = shS[oc + 1];
                if (r0 < 484) {
                    stg[r0 * 33 + oc]     = fmaxf(acc[i][n][0] * s0 + h0, 0.f);
                    stg[r0 * 33 + oc + 1] = fmaxf(acc[i][n][1] * s1 + h1, 0.f);
                }
                if (r1 < 484) {
                    stg[r1 * 33 + oc]     = fmaxf(acc[i][n][2] * s0 + h0, 0.f);
                    stg[r1 * 33 + oc + 1] = fmaxf(acc[i][n][3] * s1 + h1, 0.f);
                }
            }
        }
    }
    __syncthreads();
    for (int i = t; i < 3630; i += 256) {
        int oc = i / 121, pos = i % 121;
        int py = pos / 11, px = pos % 11;
        int p00 = (2 * py) * 22 + 2 * px;
        float v = fmaxf(fmaxf(stg[p00 * 33 + oc], stg[(p00 + 1) * 33 + oc]),
                        fmaxf(stg[(p00 + 22) * 33 + oc], stg[(p00 + 23) * 33 + oc]));
        g_p2[(((size_t)b * C2 + oc) * P2 + py) * P2 + px] = v;
    }
}

// ---------------- kernel 3: FC1 K-split GEMM ----------------
#define KC 30
__global__ __launch_bounds__(128) void fc1_kernel(const float* __restrict__ w)
{
    __shared__ __align__(16) float As[KC * 32];
    __shared__ __align__(16) float Bs[KC * 128];
    const int t = threadIdx.x;
    const int mt = blockIdx.x, nt = blockIdx.y, kz = blockIdx.z;
    const int tx = t & 31, ty = t >> 5;

    float acc[8][4];
    #pragma unroll
    for (int i = 0; i < 8; i++)
        { acc[i][0]=0.f; acc[i][1]=0.f; acc[i][2]=0.f; acc[i][3]=0.f; }

    const float* act = g_p2 + (size_t)mt * 32 * FC1_IN;
    const int kc0 = kz * 11;

    for (int kc = kc0; kc < kc0 + 11; kc++) {
        for (int i = t; i < KC * 32; i += 128) {
            int bb = i / KC, k = i % KC;
            As[k * 32 + bb] = act[bb * FC1_IN + kc * KC + k];
        }
        for (int i = t; i < KC * 128; i += 128) {
            int o = i / KC, k = i % KC;
            int go = nt * 128 + o;
            Bs[k * 128 + o] = (go < FC1_OUT) ? w[(size_t)go * FC1_IN + kc * KC + k] : 0.f;
        }
        __syncthreads();
        #pragma unroll 1
        for (int k = 0; k < KC; k++) {
            float4 bv = *(const float4*)&Bs[k * 128 + tx * 4];
            float4 a0 = *(const float4*)&As[k * 32 + ty * 8];
            float4 a1 = *(const float4*)&As[k * 32 + ty * 8 + 4];
            const float av[8] = {a0.x, a0.y, a0.z, a0.w, a1.x, a1.y, a1.z, a1.w};
            #pragma unroll
            for (int i = 0; i < 8; i++) {
                acc[i][0] += av[i] * bv.x;
                acc[i][1] += av[i] * bv.y;
                acc[i][2] += av[i] * bv.z;
                acc[i][3] += av[i] * bv.w;
            }
        }
        __syncthreads();
    }
    float* dst = g_fc1p + (size_t)kz * B * FC1_OUT;
    #pragma unroll
    for (int i = 0; i < 8; i++) {
        const int bb = mt * 32 + ty * 8 + i;
        #pragma unroll
        for (int j = 0; j < 4; j++) {
            int o = nt * 128 + tx * 4 + j;
            if (o < FC1_OUT)
                dst[(size_t)bb * FC1_OUT + o] = acc[i][j];
        }
    }
}

// ---------------- kernel 4: FC2 + sigmoid ----------------
__global__ __launch_bounds__(256) void fc2_kernel(
    const float* __restrict__ fc1b,
    const float* __restrict__ w2, const float* __restrict__ b2,
    float* __restrict__ out)
{
    const int warp = threadIdx.x >> 5, lane = threadIdx.x & 31;
    const int b = blockIdx.x * 8 + warp;
    const size_t PS = (size_t)B * FC1_OUT;
    const float* base = g_fc1p + (size_t)b * FC1_OUT;
    float s0 = 0.f, s1 = 0.f;
    for (int o = lane; o < FC1_OUT; o += 32) {
        float v = fc1b[o];
        #pragma unroll
        for (int p = 0; p < KSPLIT; p++)
            v += base[p * PS + o];
        v = fmaxf(v, 0.f);
        s0 += v * w2[o];
        s1 += v * w2[FC1_OUT + o];
    }
    #pragma unroll
    for (int d = 16; d > 0; d >>= 1) {
        s0 += __shfl_xor_sync(0xFFFFFFFFu, s0, d);
        s1 += __shfl_xor_sync(0xFFFFFFFFu, s1, d);
    }
    if (lane == 0) {
        out[2 * b + 0] = 1.f / (1.f + expf(-(s0 + b2[0])));
        out[2 * b + 1] = 1.f / (1.f + expf(-(s1 + b2[1])));
    }
}

// ---------------- launch ----------------
extern "C" void kernel_launch(void* const* d_in, const int* in_sizes, int n_in,
                              void* d_out, int out_size)
{
    const float* x       = (const float*)d_in[0];
    const float* log_s   = (const float*)d_in[1];
    const float* log_a   = (const float*)d_in[2];
    const float* log_d   = (const float*)d_in[3];
    const float* log_r   = (const float*)d_in[4];
    const float* conv1_w = (const float*)d_in[5];
    const float* conv1_b = (const float*)d_in[6];
    const float* bn1_g   = (const float*)d_in[7];
    const float* bn1_b   = (const float*)d_in[8];
    const float* bn1_m   = (const float*)d_in[9];
    const float* bn1_v   = (const float*)d_in[10];
    const float* conv2_w = (const float*)d_in[11];
    const float* conv2_b = (const float*)d_in[12];
    const float* bn2_g   = (const float*)d_in[13];
    const float* bn2_b   = (const float*)d_in[14];
    const float* bn2_m   = (const float*)d_in[15];
    const float* bn2_v   = (const float*)d_in[16];
    const float* fc1_w   = (const float*)d_in[17];
    const float* fc1_b   = (const float*)d_in[18];
    const float* fc2_w   = (const float*)d_in[19];
    const float* fc2_b   = (const float*)d_in[20];
    float* out = (float*)d_out;

    static int smem_set = 0;
    if (!smem_set) {
        cudaFuncSetAttribute(conv2_mma_kernel,
                             cudaFuncAttributeMaxDynamicSharedMemorySize, SM_TOT);
        smem_set = 1;
    }

    prep_b_frag<<<53, 256>>>(conv2_w);
    conv1_pcen_kernel<<<B, 288>>>(x, log_s, log_a, log_d, log_r,
                                  conv1_w, conv1_b, bn1_g, bn1_b, bn1_m, bn1_v);
    conv2_mma_kernel<<<B, 256, SM_TOT>>>(conv2_b, bn2_g, bn2_b, bn2_m, bn2_v);
    fc1_kernel<<<dim3(64, 2, KSPLIT), 128>>>(fc1_w);
    fc2_kernel<<<B / 8, 256>>>(fc1_b, fc2_w, fc2_b, out);
}

// round 7
// speedup vs baseline: 1.6210x; 1.5632x over previous
#include <cuda_runtime.h>
#include <cuda_bf16.h>
#include <math.h>
#include <stdint.h>

#define B 2048
#define C1 15
#define C2 30
#define P1 29
#define P2 11
#define IN2P 32
#define FC1_IN (30*11*11)
#define FC1_OUT 200
#define KSPLIT 8

typedef unsigned long long ull;
typedef __nv_bfloat16 bf16;
typedef uint16_t u16;
typedef uint32_t u32;

// ---------------- f32x2 helpers (conv1) ----------------
__device__ __forceinline__ ull pack_dup(float v) {
    ull r; unsigned int u = __float_as_uint(v);
    asm("mov.b64 %0, {%1, %2};" : "=l"(r) : "r"(u), "r"(u));
    return r;
}
__device__ __forceinline__ void ffma2(ull& d, ull a, ull b) {
    asm("fma.rn.f32x2 %0, %1, %2, %3;" : "=l"(d) : "l"(a), "l"(b), "l"(d));
}
__device__ __forceinline__ float2 unpack2(ull p) {
    unsigned int lo, hi;
    asm("mov.b64 {%0, %1}, %2;" : "=r"(lo), "=r"(hi) : "l"(p));
    return make_float2(__uint_as_float(lo), __uint_as_float(hi));
}

// ---------------- warp mma m16n8k16 bf16 ----------------
__device__ __forceinline__ void mma_bf16(float* d, u32 a0, u32 a1, u32 a2, u32 a3,
                                         u32 b0, u32 b1) {
    asm volatile(
        "mma.sync.aligned.m16n8k16.row.col.f32.bf16.bf16.f32 "
        "{%0,%1,%2,%3}, {%4,%5,%6,%7}, {%8,%9}, {%0,%1,%2,%3};"
        : "+f"(d[0]), "+f"(d[1]), "+f"(d[2]), "+f"(d[3])
        : "r"(a0), "r"(a1), "r"(a2), "r"(a3), "r"(b0), "r"(b1));
}

__device__ __forceinline__ u16 bf16_bits(float v) {
    return __bfloat16_as_ushort(__float2bfloat16(v));
}

// ---------------- scratch ----------------
__device__ float g_p1[B * C1 * P1 * IN2P];
__device__ float g_p2[B * C2 * P2 * P2];
__device__ float g_fc1p[KSPLIT * B * FC1_OUT];
// [ks(60)][nt(4)][lane(32)] x {b0h,b1h,b0l,b1l}
__device__ __align__(16) u32 g_Bfrag2[60 * 4 * 32 * 4];

// ---------------- kernel 0: prep conv2 B fragments ----------------
__global__ void prep_b_frag(const float* __restrict__ w2)
{
    int idx = blockIdx.x * 256 + threadIdx.x;   // (ks*4+nt)*32 + lane
    if (idx >= 7680) return;
    int lane = idx & 31, nt = (idx >> 5) & 3, ks = idx >> 7;
    int ic = ks >> 2, dyp = ks & 3;
    int oc = nt * 8 + (lane >> 2), k0 = (lane & 3) * 2;
    int dy0 = dyp * 2, dy1 = dy0 + 1;

    float v[4] = {0.f, 0.f, 0.f, 0.f};   // {dy0:k0, dy0:k0+1, dy1:k0, dy1:k0+1}
    if (oc < C2) {
        const float* wb = w2 + (oc * C1 + ic) * 49;
        v[0] = wb[dy0 * 7 + k0];
        if (k0 + 1 < 7) v[1] = wb[dy0 * 7 + k0 + 1];
        if (dy1 < 7) {
            v[2] = wb[dy1 * 7 + k0];
            if (k0 + 1 < 7) v[3] = wb[dy1 * 7 + k0 + 1];
        }
    }
    u16 h[4], l[4];
    #pragma unroll
    for (int i = 0; i < 4; i++) {
        h[i] = bf16_bits(v[i]);
        l[i] = bf16_bits(v[i] - __uint_as_float((u32)h[i] << 16));
    }
    uint4 q;
    q.x = (u32)h[0] | ((u32)h[1] << 16);   // b0 hi
    q.y = (u32)h[2] | ((u32)h[3] << 16);   // b1 hi
    q.z = (u32)l[0] | ((u32)l[1] << 16);   // b0 lo
    q.w = (u32)l[2] | ((u32)l[3] << 16);   // b1 lo
    ((uint4*)g_Bfrag2)[idx] = q;
}

// ---------------- kernel 1: PCEN + conv1 + BN + ReLU + pool ----------------
__global__ __launch_bounds__(288) void conv1_pcen_kernel(
    const float* __restrict__ x,
    const float* __restrict__ log_s, const float* __restrict__ log_alpha,
    const float* __restrict__ log_delta, const float* __restrict__ log_r,
    const float* __restrict__ w1, const float* __restrict__ b1,
    const float* __restrict__ g,  const float* __restrict__ be,
    const float* __restrict__ mu, const float* __restrict__ va)
{
    __shared__ __align__(16) float inS[64 * 66];
    __shared__ __align__(16) float wT[49 * 16];
    __shared__ float scS[C1], shS[C1];

    const int b = blockIdx.x, t = threadIdx.x;
    const float* xb = x + (size_t)b * 4096;

    for (int i = t; i < 4096; i += 288)
        inS[(i >> 6) * 66 + (i & 63)] = xb[i];
    for (int i = t; i < 49 * 16; i += 288) {
        int k = i >> 4, c = i & 15;
        wT[i] = (c < C1) ? w1[c * 49 + k] : 0.f;
    }
    if (t < C1) {
        float inv = g[t] * rsqrtf(va[t] + 1e-5f);
        scS[t] = inv;
        shS[t] = (b1[t] - mu[t]) * inv + be[t];
    }
    __syncthreads();

    if (t < 64) {
        const float s     = expf(log_s[0]);
        const float alpha = expf(log_alpha[0]);
        const float delta = expf(log_delta[0]);
        const float r     = expf(log_r[0]);
        const float oms   = 1.0f - s;
        const float dr    = powf(delta, r);
        float* row = inS + t * 66;
        float m = 0.0f;
        #pragma unroll 4
        for (int w = 0; w < 64; w++) {
            float xv = row[w];
            m = (w == 0) ? s * xv : oms * m + s * xv;
            float Ma = __powf(m + 1e-6f, alpha);
            row[w] = __powf(__fdividef(xv, Ma) + delta, r) - dr;
        }
    }
    __syncthreads();

    for (int pos = t; pos < P1 * P1; pos += 288) {
        const int pi = pos / P1, pj = pos % P1;
        ull acc[8][4];
        #pragma unroll
        for (int q = 0; q < 8; q++)
            { acc[q][0]=0ull; acc[q][1]=0ull; acc[q][2]=0ull; acc[q][3]=0ull; }
        const float* ip = inS + (2 * pi) * 66 + 2 * pj;

        #pragma unroll 1
        for (int dy = 0; dy < 7; dy++) {
            float rA[8], rB[8];
            const float* r0 = ip + dy * 66;
            #pragma unroll
            for (int k = 0; k < 4; k++) {
                float2 a = *(const float2*)&r0[2 * k];
                float2 bq = *(const float2*)&r0[66 + 2 * k];
                rA[2 * k] = a.x;  rA[2 * k + 1] = a.y;
                rB[2 * k] = bq.x; rB[2 * k + 1] = bq.y;
            }
            ull dA[8], dB[8];
            #pragma unroll
            for (int k = 0; k < 8; k++) { dA[k] = pack_dup(rA[k]); dB[k] = pack_dup(rB[k]); }
            #pragma unroll
            for (int dx = 0; dx < 7; dx++) {
                const ull* wq = (const ull*)(wT + (dy * 7 + dx) * 16);
                #pragma unroll
                for (int q = 0; q < 8; q++) {
                    ull w = wq[q];
                    ffma2(acc[q][0], dA[dx],     w);
                    ffma2(acc[q][1], dA[dx + 1], w);
                    ffma2(acc[q][2], dB[dx],     w);
                    ffma2(acc[q][3], dB[dx + 1], w);
                }
            }
        }
        float* ob = g_p1 + (size_t)b * (C1 * P1 * IN2P) + pi * IN2P + pj;
        #pragma unroll
        for (int q = 0; q < 8; q++) {
            float2 v0 = unpack2(acc[q][0]);
            float2 v1 = unpack2(acc[q][1]);
            float2 v2 = unpack2(acc[q][2]);
            float2 v3 = unpack2(acc[q][3]);
            const int c0 = 2 * q, c1 = 2 * q + 1;
            {
                float sc = scS[c0], sh = shS[c0];
                float a0 = fmaxf(v0.x * sc + sh, 0.f);
                float a1 = fmaxf(v1.x * sc + sh, 0.f);
                float a2 = fmaxf(v2.x * sc + sh, 0.f);
                float a3 = fmaxf(v3.x * sc + sh, 0.f);
                ob[c0 * (P1 * IN2P)] = fmaxf(fmaxf(a0, a1), fmaxf(a2, a3));
            }
            if (c1 < C1) {
                float sc = scS[c1], sh = shS[c1];
                float a0 = fmaxf(v0.y * sc + sh, 0.f);
                float a1 = fmaxf(v1.y * sc + sh, 0.f);
                float a2 = fmaxf(v2.y * sc + sh, 0.f);
                float a3 = fmaxf(v3.y * sc + sh, 0.f);
                ob[c1 * (P1 * IN2P)] = fmaxf(fmaxf(a0, a1), fmaxf(a2, a3));
            }
        }
    }
}

// ---------------- kernel 2: conv2 via warp mma (bf16 k16, 3-term split) ----------------
// planes: hi-even | hi-odd | lo-even | lo-odd, each [15][29][16] u32 = 27840 B
#define PL_U32 6960
#define SM_PHE 0
#define SM_PLE 55680
#define SM_SC  111360
#define SM_SH  111488
#define SM_TOT2 111616

__global__ __launch_bounds__(256, 2) void conv2_mma_kernel(
    const float* __restrict__ b2,
    const float* __restrict__ g,  const float* __restrict__ be,
    const float* __restrict__ mu, const float* __restrict__ va)
{
    extern __shared__ __align__(16) char smem[];
    u16* hE16 = (u16*)(smem + SM_PHE);           // even plane (hi)
    u16* lE16 = (u16*)(smem + SM_PLE);
    const u32* pH = (const u32*)(smem + SM_PHE); // even+odd contiguous
    const u32* pL = (const u32*)(smem + SM_PLE);
    float* scS = (float*)(smem + SM_SC);
    float* shS = (float*)(smem + SM_SH);

    const int t = threadIdx.x, w = t >> 5, lane = t & 31;
    const int b = blockIdx.x;

    // build hi/lo bf16 planes, even + odd parity copies
    {
        const float* src = g_p1 + (size_t)b * 13920;
        u16* hO16 = hE16 + 13920;
        u16* lO16 = lE16 + 13920;
        for (int i = t; i < 13920; i += 256) {
            float v = src[i];
            u16 h = bf16_bits(v);
            u16 l = bf16_bits(v - __uint_as_float((u32)h << 16));
            hE16[i] = h; lE16[i] = l;
            if (i > 0) { hO16[i - 1] = h; lO16[i - 1] = l; }
        }
        if (t == 0) { hO16[13919] = 0; lO16[13919] = 0; }
    }
    if (t < C2) {
        float inv = g[t] * rsqrtf(va[t] + 1e-5f);
        scS[t] = inv;
        shS[t] = (b2[t] - mu[t]) * inv + be[t];
    }
    __syncthreads();

    // per-i combined plane offsets (parity folded in: odd plane = +PL_U32)
    int c0[4], c1[4];
    #pragma unroll
    for (int i = 0; i < 4; i++) {
        int mt = w * 4 + i; if (mt > 30) mt = 30;
        int p0 = mt * 16 + (lane >> 2); if (p0 > 483) p0 = 483;
        int p1 = p0 + 8;                if (p1 > 483) p1 = 483;
        int y0 = p0 / 22, x0 = p0 - y0 * 22;
        int y1 = p1 / 22, x1 = p1 - y1 * 22;
        int dx0 = (lane & 3) * 2;
        c0[i] = (x0 & 1) * PL_U32 + y0 * 16 + ((x0 + dx0 - (x0 & 1)) >> 1);
        c1[i] = (x1 & 1) * PL_U32 + y1 * 16 + ((x1 + dx0 - (x1 & 1)) >> 1);
    }

    float acc[4][4][4];
    #pragma unroll
    for (int i = 0; i < 4; i++)
        #pragma unroll
        for (int n = 0; n < 4; n++)
            { acc[i][n][0]=0.f; acc[i][n][1]=0.f; acc[i][n][2]=0.f; acc[i][n][3]=0.f; }

    const uint4* bfr = (const uint4*)g_Bfrag2;

    #pragma unroll 1
    for (int ic = 0; ic < 15; ic++) {
        #pragma unroll 1
        for (int dyp = 0; dyp < 4; dyp++) {
            const int ks = ic * 4 + dyp;
            uint4 q0 = bfr[(ks * 4 + 0) * 32 + lane];
            uint4 q1 = bfr[(ks * 4 + 1) * 32 + lane];
            uint4 q2 = bfr[(ks * 4 + 2) * 32 + lane];
            uint4 q3 = bfr[(ks * 4 + 3) * 32 + lane];
            const int kb0 = (ic * 29 + dyp * 2) * 16;
            const int kb1 = kb0 + 16;
            #pragma unroll
            for (int i = 0; i < 4; i++) {
                u32 ah0 = pH[c0[i] + kb0], ah1 = pH[c1[i] + kb0];
                u32 ah2 = pH[c0[i] + kb1], ah3 = pH[c1[i] + kb1];
                u32 al0 = pL[c0[i] + kb0], al1 = pL[c1[i] + kb0];
                u32 al2 = pL[c0[i] + kb1], al3 = pL[c1[i] + kb1];
                mma_bf16(acc[i][0], ah0, ah1, ah2, ah3, q0.x, q0.y);
                mma_bf16(acc[i][0], ah0, ah1, ah2, ah3, q0.z, q0.w);
                mma_bf16(acc[i][0], al0, al1, al2, al3, q0.x, q0.y);
                mma_bf16(acc[i][1], ah0, ah1, ah2, ah3, q1.x, q1.y);
                mma_bf16(acc[i][1], ah0, ah1, ah2, ah3, q1.z, q1.w);
                mma_bf16(acc[i][1], al0, al1, al2, al3, q1.x, q1.y);
                mma_bf16(acc[i][2], ah0, ah1, ah2, ah3, q2.x, q2.y);
                mma_bf16(acc[i][2], ah0, ah1, ah2, ah3, q2.z, q2.w);
                mma_bf16(acc[i][2], al0, al1, al2, al3, q2.x, q2.y);
                mma_bf16(acc[i][3], ah0, ah1, ah2, ah3, q3.x, q3.y);
                mma_bf16(acc[i][3], ah0, ah1, ah2, ah3, q3.z, q3.w);
                mma_bf16(acc[i][3], al0, al1, al2, al3, q3.x, q3.y);
            }
        }
    }

    __syncthreads();                       // planes dead; reuse as stage
    float* stg = (float*)smem;             // [484][33]
    #pragma unroll
    for (int i = 0; i < 4; i++) {
        int mt = w * 4 + i; if (mt > 30) mt = 30;
        int r0 = mt * 16 + (lane >> 2), r1 = r0 + 8;
        #pragma unroll
        for (int n = 0; n < 4; n++) {
            int oc = n * 8 + (lane & 3) * 2;
            if (oc < C2) {
                float s0 = scS[oc], h0 = shS[oc];
                float s1 = scS[oc + 1], h1 = shS[oc + 1];
                if (r0 < 484) {
                    stg[r0 * 33 + oc]     = fmaxf(acc[i][n][0] * s0 + h0, 0.f);
                    stg[r0 * 33 + oc + 1] = fmaxf(acc[i][n][1] * s1 + h1, 0.f);
                }
                if (r1 < 484) {
                    stg[r1 * 33 + oc]     = fmaxf(acc[i][n][2] * s0 + h0, 0.f);
                    stg[r1 * 33 + oc + 1] = fmaxf(acc[i][n][3] * s1 + h1, 0.f);
                }
            }
        }
    }
    __syncthreads();
    for (int i = t; i < 3630; i += 256) {
        int oc = i / 121, pos = i % 121;
        int py = pos / 11, px = pos % 11;
        int p00 = (2 * py) * 22 + 2 * px;
        float v = fmaxf(fmaxf(stg[p00 * 33 + oc], stg[(p00 + 1) * 33 + oc]),
                        fmaxf(stg[(p00 + 22) * 33 + oc], stg[(p00 + 23) * 33 + oc]));
        g_p2[(((size_t)b * C2 + oc) * P2 + py) * P2 + px] = v;
    }
}

// ---------------- kernel 3: FC1 (128x128 tile, 8x8 per thread, K-split 8) ----------------
#define KC 30
__global__ __launch_bounds__(256) void fc1_kernel(const float* __restrict__ w)
{
    __shared__ __align__(16) float As[KC * 128];
    __shared__ __align__(16) float Bs[KC * 128];
    const int t = threadIdx.x;
    const int mt = blockIdx.x;      // 0..15 (128 batches)
    const int nt = blockIdx.y;      // 0..1  (128 outs)
    const int kz = blockIdx.z;      // 0..7
    const int tx = t & 15, ty = t >> 4;

    float acc[8][8];
    #pragma unroll
    for (int i = 0; i < 8; i++)
        #pragma unroll
        for (int j = 0; j < 8; j++) acc[i][j] = 0.f;

    const float* act = g_p2 + (size_t)mt * 128 * FC1_IN;
    const int kc0 = kz * 15;
    const int nkc = (kz == 7) ? 16 : 15;   // 121 = 7*15 + 16

    for (int kc = kc0; kc < kc0 + nkc; kc++) {
        for (int i = t; i < KC * 128; i += 256) {
            int m = i / KC, k = i % KC;
            As[k * 128 + m] = act[(size_t)m * FC1_IN + kc * KC + k];
        }
        for (int i = t; i < KC * 128; i += 256) {
            int o = i / KC, k = i % KC;
            int go = nt * 128 + o;
            Bs[k * 128 + o] = (go < FC1_OUT) ? w[(size_t)go * FC1_IN + kc * KC + k] : 0.f;
        }
        __syncthreads();
        #pragma unroll 1
        for (int k = 0; k < KC; k++) {
            float4 a0 = *(const float4*)&As[k * 128 + ty * 8];
            float4 a1 = *(const float4*)&As[k * 128 + ty * 8 + 4];
            float4 b0 = *(const float4*)&Bs[k * 128 + tx * 8];
            float4 b1 = *(const float4*)&Bs[k * 128 + tx * 8 + 4];
            const float av[8] = {a0.x, a0.y, a0.z, a0.w, a1.x, a1.y, a1.z, a1.w};
            const float bv[8] = {b0.x, b0.y, b0.z, b0.w, b1.x, b1.y, b1.z, b1.w};
            #pragma unroll
            for (int i = 0; i < 8; i++)
                #pragma unroll
                for (int j = 0; j < 8; j++)
                    acc[i][j] += av[i] * bv[j];
        }
        __syncthreads();
    }
    float* dst = g_fc1p + (size_t)kz * B * FC1_OUT;
    #pragma unroll
    for (int i = 0; i < 8; i++) {
        const int bb = mt * 128 + ty * 8 + i;
        #pragma unroll
        for (int j = 0; j < 8; j++) {
            int o = nt * 128 + tx * 8 + j;
            if (o < FC1_OUT)
                dst[(size_t)bb * FC1_OUT + o] = acc[i][j];
        }
    }
}

// ---------------- kernel 4: FC2 + sigmoid ----------------
__global__ __launch_bounds__(256) void fc2_kernel(
    const float* __restrict__ fc1b,
    const float* __restrict__ w2, const float* __restrict__ b2,
    float* __restrict__ out)
{
    const int warp = threadIdx.x >> 5, lane = threadIdx.x & 31;
    const int b = blockIdx.x * 8 + warp;
    const size_t PS = (size_t)B * FC1_OUT;
    const float* base = g_fc1p + (size_t)b * FC1_OUT;
    float s0 = 0.f, s1 = 0.f;
    for (int o = lane; o < FC1_OUT; o += 32) {
        float v = fc1b[o];
        #pragma unroll
        for (int p = 0; p < KSPLIT; p++)
            v += base[p * PS + o];
        v = fmaxf(v, 0.f);
        s0 += v * w2[o];
        s1 += v * w2[FC1_OUT + o];
    }
    #pragma unroll
    for (int d = 16; d > 0; d >>= 1) {
        s0 += __shfl_xor_sync(0xFFFFFFFFu, s0, d);
        s1 += __shfl_xor_sync(0xFFFFFFFFu, s1, d);
    }
    if (lane == 0) {
        out[2 * b + 0] = 1.f / (1.f + expf(-(s0 + b2[0])));
        out[2 * b + 1] = 1.f / (1.f + expf(-(s1 + b2[1])));
    }
}

// ---------------- launch ----------------
extern "C" void kernel_launch(void* const* d_in, const int* in_sizes, int n_in,
                              void* d_out, int out_size)
{
    const float* x       = (const float*)d_in[0];
    const float* log_s   = (const float*)d_in[1];
    const float* log_a   = (const float*)d_in[2];
    const float* log_d   = (const float*)d_in[3];
    const float* log_r   = (const float*)d_in[4];
    const float* conv1_w = (const float*)d_in[5];
    const float* conv1_b = (const float*)d_in[6];
    const float* bn1_g   = (const float*)d_in[7];
    const float* bn1_b   = (const float*)d_in[8];
    const float* bn1_m   = (const float*)d_in[9];
    const float* bn1_v   = (const float*)d_in[10];
    const float* conv2_w = (const float*)d_in[11];
    const float* conv2_b = (const float*)d_in[12];
    const float* bn2_g   = (const float*)d_in[13];
    const float* bn2_b   = (const float*)d_in[14];
    const float* bn2_m   = (const float*)d_in[15];
    const float* bn2_v   = (const float*)d_in[16];
    const float* fc1_w   = (const float*)d_in[17];
    const float* fc1_b   = (const float*)d_in[18];
    const float* fc2_w   = (const float*)d_in[19];
    const float* fc2_b   = (const float*)d_in[20];
    float* out = (float*)d_out;

    static int smem_set = 0;
    if (!smem_set) {
        cudaFuncSetAttribute(conv2_mma_kernel,
                             cudaFuncAttributeMaxDynamicSharedMemorySize, SM_TOT2);
        smem_set = 1;
    }

    prep_b_frag<<<30, 256>>>(conv2_w);
    conv1_pcen_kernel<<<B, 288>>>(x, log_s, log_a, log_d, log_r,
                                  conv1_w, conv1_b, bn1_g, bn1_b, bn1_m, bn1_v);
    conv2_mma_kernel<<<B, 256, SM_TOT2>>>(conv2_b, bn2_g, bn2_b, bn2_m, bn2_v);
    fc1_kernel<<<dim3(16, 2, KSPLIT), 256>>>(fc1_w);
    fc2_kernel<<<B / 8, 256>>>(fc1_b, fc2_w, fc2_b, out);
}

// round 8
// speedup vs baseline: 1.9348x; 1.1935x over previous
#include <cuda_runtime.h>
#include <cuda_bf16.h>
#include <math.h>
#include <stdint.h>

#define B 2048
#define C1 15
#define C2 30
#define P1 29
#define P2 11
#define IN2P 32
#define FC1_IN (30*11*11)
#define FC1_OUT 200
#define KSPLIT 8
#define NKS1 227              // ceil(3630/16)

typedef unsigned long long ull;
typedef __nv_bfloat16 bf16;
typedef uint16_t u16;
typedef uint32_t u32;

// ---------------- f32x2 helpers (conv1) ----------------
__device__ __forceinline__ ull pack_dup(float v) {
    ull r; unsigned int u = __float_as_uint(v);
    asm("mov.b64 %0, {%1, %2};" : "=l"(r) : "r"(u), "r"(u));
    return r;
}
__device__ __forceinline__ void ffma2(ull& d, ull a, ull b) {
    asm("fma.rn.f32x2 %0, %1, %2, %3;" : "=l"(d) : "l"(a), "l"(b), "l"(d));
}
__device__ __forceinline__ float2 unpack2(ull p) {
    unsigned int lo, hi;
    asm("mov.b64 {%0, %1}, %2;" : "=r"(lo), "=r"(hi) : "l"(p));
    return make_float2(__uint_as_float(lo), __uint_as_float(hi));
}

// ---------------- warp mma m16n8k16 bf16 ----------------
__device__ __forceinline__ void mma_bf16(float* d, u32 a0, u32 a1, u32 a2, u32 a3,
                                         u32 b0, u32 b1) {
    asm volatile(
        "mma.sync.aligned.m16n8k16.row.col.f32.bf16.bf16.f32 "
        "{%0,%1,%2,%3}, {%4,%5,%6,%7}, {%8,%9}, {%0,%1,%2,%3};"
        : "+f"(d[0]), "+f"(d[1]), "+f"(d[2]), "+f"(d[3])
        : "r"(a0), "r"(a1), "r"(a2), "r"(a3), "r"(b0), "r"(b1));
}

__device__ __forceinline__ u16 bf16_bits(float v) {
    return __bfloat16_as_ushort(__float2bfloat16(v));
}

// ---------------- scratch ----------------
__device__ float g_p1[B * C1 * P1 * IN2P];
__device__ float g_fc1p[KSPLIT * B * FC1_OUT];
__device__ __align__(16) u32 g_Bfrag2[60 * 4 * 32 * 4];      // conv2 B frags
__device__ __align__(16) uint4 g_W1frag[NKS1 * 25 * 32];      // fc1 W frags (2.9MB)
__device__ __align__(4) u16 g_p2h[B * FC1_IN + 64];           // fc1 A hi plane
__device__ __align__(4) u16 g_p2l[B * FC1_IN + 64];           // fc1 A lo plane

// ---------------- kernel 0a: prep conv2 B fragments ----------------
__global__ void prep_b_frag(const float* __restrict__ w2)
{
    int idx = blockIdx.x * 256 + threadIdx.x;
    if (idx >= 7680) return;
    int lane = idx & 31, nt = (idx >> 5) & 3, ks = idx >> 7;
    int ic = ks >> 2, dyp = ks & 3;
    int oc = nt * 8 + (lane >> 2), k0 = (lane & 3) * 2;
    int dy0 = dyp * 2, dy1 = dy0 + 1;

    float v[4] = {0.f, 0.f, 0.f, 0.f};
    if (oc < C2) {
        const float* wb = w2 + (oc * C1 + ic) * 49;
        v[0] = wb[dy0 * 7 + k0];
        if (k0 + 1 < 7) v[1] = wb[dy0 * 7 + k0 + 1];
        if (dy1 < 7) {
            v[2] = wb[dy1 * 7 + k0];
            if (k0 + 1 < 7) v[3] = wb[dy1 * 7 + k0 + 1];
        }
    }
    u16 h[4], l[4];
    #pragma unroll
    for (int i = 0; i < 4; i++) {
        h[i] = bf16_bits(v[i]);
        l[i] = bf16_bits(v[i] - __uint_as_float((u32)h[i] << 16));
    }
    uint4 q;
    q.x = (u32)h[0] | ((u32)h[1] << 16);
    q.y = (u32)h[2] | ((u32)h[3] << 16);
    q.z = (u32)l[0] | ((u32)l[1] << 16);
    q.w = (u32)l[2] | ((u32)l[3] << 16);
    ((uint4*)g_Bfrag2)[idx] = q;
}

// ---------------- kernel 0b: prep fc1 W fragments ----------------
__global__ void prep_w1_frag(const float* __restrict__ w)
{
    int idx = blockIdx.x * 256 + threadIdx.x;
    if (idx >= NKS1 * 25 * 32) return;
    int lane = idx & 31;
    int nt = (idx >> 5) % 25;
    int ks = idx / (25 * 32);
    int o = nt * 8 + (lane >> 2);
    int k0 = ks * 16 + (lane & 3) * 2;
    const float* wr = w + (size_t)o * FC1_IN;

    float v[4];
    v[0] = (k0     < FC1_IN) ? wr[k0]     : 0.f;
    v[1] = (k0 + 1 < FC1_IN) ? wr[k0 + 1] : 0.f;
    v[2] = (k0 + 8 < FC1_IN) ? wr[k0 + 8] : 0.f;
    v[3] = (k0 + 9 < FC1_IN) ? wr[k0 + 9] : 0.f;
    u16 h[4], l[4];
    #pragma unroll
    for (int i = 0; i < 4; i++) {
        h[i] = bf16_bits(v[i]);
        l[i] = bf16_bits(v[i] - __uint_as_float((u32)h[i] << 16));
    }
    uint4 q;
    q.x = (u32)h[0] | ((u32)h[1] << 16);
    q.y = (u32)h[2] | ((u32)h[3] << 16);
    q.z = (u32)l[0] | ((u32)l[1] << 16);
    q.w = (u32)l[2] | ((u32)l[3] << 16);
    g_W1frag[idx] = q;
}

// ---------------- kernel 1: PCEN + conv1 + BN + ReLU + pool ----------------
__global__ __launch_bounds__(288) void conv1_pcen_kernel(
    const float* __restrict__ x,
    const float* __restrict__ log_s, const float* __restrict__ log_alpha,
    const float* __restrict__ log_delta, const float* __restrict__ log_r,
    const float* __restrict__ w1, const float* __restrict__ b1,
    const float* __restrict__ g,  const float* __restrict__ be,
    const float* __restrict__ mu, const float* __restrict__ va)
{
    __shared__ __align__(16) float inS[64 * 66];
    __shared__ __align__(16) float wT[49 * 16];
    __shared__ float scS[C1], shS[C1];

    const int b = blockIdx.x, t = threadIdx.x;
    const float* xb = x + (size_t)b * 4096;

    for (int i = t; i < 4096; i += 288)
        inS[(i >> 6) * 66 + (i & 63)] = xb[i];
    for (int i = t; i < 49 * 16; i += 288) {
        int k = i >> 4, c = i & 15;
        wT[i] = (c < C1) ? w1[c * 49 + k] : 0.f;
    }
    if (t < C1) {
        float inv = g[t] * rsqrtf(va[t] + 1e-5f);
        scS[t] = inv;
        shS[t] = (b1[t] - mu[t]) * inv + be[t];
    }
    __syncthreads();

    if (t < 64) {
        const float s     = expf(log_s[0]);
        const float alpha = expf(log_alpha[0]);
        const float delta = expf(log_delta[0]);
        const float r     = expf(log_r[0]);
        const float oms   = 1.0f - s;
        const float dr    = powf(delta, r);
        float* row = inS + t * 66;
        float m = 0.0f;
        #pragma unroll 4
        for (int w = 0; w < 64; w++) {
            float xv = row[w];
            m = (w == 0) ? s * xv : oms * m + s * xv;
            float Ma = __powf(m + 1e-6f, alpha);
            row[w] = __powf(__fdividef(xv, Ma) + delta, r) - dr;
        }
    }
    __syncthreads();

    for (int pos = t; pos < P1 * P1; pos += 288) {
        const int pi = pos / P1, pj = pos % P1;
        ull acc[8][4];
        #pragma unroll
        for (int q = 0; q < 8; q++)
            { acc[q][0]=0ull; acc[q][1]=0ull; acc[q][2]=0ull; acc[q][3]=0ull; }
        const float* ip = inS + (2 * pi) * 66 + 2 * pj;

        #pragma unroll 1
        for (int dy = 0; dy < 7; dy++) {
            float rA[8], rB[8];
            const float* r0 = ip + dy * 66;
            #pragma unroll
            for (int k = 0; k < 4; k++) {
                float2 a = *(const float2*)&r0[2 * k];
                float2 bq = *(const float2*)&r0[66 + 2 * k];
                rA[2 * k] = a.x;  rA[2 * k + 1] = a.y;
                rB[2 * k] = bq.x; rB[2 * k + 1] = bq.y;
            }
            ull dA[8], dB[8];
            #pragma unroll
            for (int k = 0; k < 8; k++) { dA[k] = pack_dup(rA[k]); dB[k] = pack_dup(rB[k]); }
            #pragma unroll
            for (int dx = 0; dx < 7; dx++) {
                const ull* wq = (const ull*)(wT + (dy * 7 + dx) * 16);
                #pragma unroll
                for (int q = 0; q < 8; q++) {
                    ull w = wq[q];
                    ffma2(acc[q][0], dA[dx],     w);
                    ffma2(acc[q][1], dA[dx + 1], w);
                    ffma2(acc[q][2], dB[dx],     w);
                    ffma2(acc[q][3], dB[dx + 1], w);
                }
            }
        }
        float* ob = g_p1 + (size_t)b * (C1 * P1 * IN2P) + pi * IN2P + pj;
        #pragma unroll
        for (int q = 0; q < 8; q++) {
            float2 v0 = unpack2(acc[q][0]);
            float2 v1 = unpack2(acc[q][1]);
            float2 v2 = unpack2(acc[q][2]);
            float2 v3 = unpack2(acc[q][3]);
            const int c0 = 2 * q, c1 = 2 * q + 1;
            {
                float sc = scS[c0], sh = shS[c0];
                float a0 = fmaxf(v0.x * sc + sh, 0.f);
                float a1 = fmaxf(v1.x * sc + sh, 0.f);
                float a2 = fmaxf(v2.x * sc + sh, 0.f);
                float a3 = fmaxf(v3.x * sc + sh, 0.f);
                ob[c0 * (P1 * IN2P)] = fmaxf(fmaxf(a0, a1), fmaxf(a2, a3));
            }
            if (c1 < C1) {
                float sc = scS[c1], sh = shS[c1];
                float a0 = fmaxf(v0.y * sc + sh, 0.f);
                float a1 = fmaxf(v1.y * sc + sh, 0.f);
                float a2 = fmaxf(v2.y * sc + sh, 0.f);
                float a3 = fmaxf(v3.y * sc + sh, 0.f);
                ob[c1 * (P1 * IN2P)] = fmaxf(fmaxf(a0, a1), fmaxf(a2, a3));
            }
        }
    }
}

// ---------------- kernel 2: conv2 via warp mma (bf16 k16, 3-term split) ----------------
#define PL_U32 6960
#define SM_PHE 0
#define SM_PLE 55680
#define SM_SC  111360
#define SM_SH  111488
#define SM_TOT2 111616

__global__ __launch_bounds__(256, 2) void conv2_mma_kernel(
    const float* __restrict__ b2,
    const float* __restrict__ g,  const float* __restrict__ be,
    const float* __restrict__ mu, const float* __restrict__ va)
{
    extern __shared__ __align__(16) char smem[];
    u16* hE16 = (u16*)(smem + SM_PHE);
    u16* lE16 = (u16*)(smem + SM_PLE);
    const u32* pH = (const u32*)(smem + SM_PHE);
    const u32* pL = (const u32*)(smem + SM_PLE);
    float* scS = (float*)(smem + SM_SC);
    float* shS = (float*)(smem + SM_SH);

    const int t = threadIdx.x, w = t >> 5, lane = t & 31;
    const int b = blockIdx.x;

    {
        const float* src = g_p1 + (size_t)b * 13920;
        u16* hO16 = hE16 + 13920;
        u16* lO16 = lE16 + 13920;
        for (int i = t; i < 13920; i += 256) {
            float v = src[i];
            u16 h = bf16_bits(v);
            u16 l = bf16_bits(v - __uint_as_float((u32)h << 16));
            hE16[i] = h; lE16[i] = l;
            if (i > 0) { hO16[i - 1] = h; lO16[i - 1] = l; }
        }
        if (t == 0) { hO16[13919] = 0; lO16[13919] = 0; }
    }
    if (t < C2) {
        float inv = g[t] * rsqrtf(va[t] + 1e-5f);
        scS[t] = inv;
        shS[t] = (b2[t] - mu[t]) * inv + be[t];
    }
    __syncthreads();

    int c0[4], c1[4];
    #pragma unroll
    for (int i = 0; i < 4; i++) {
        int mt = w * 4 + i; if (mt > 30) mt = 30;
        int p0 = mt * 16 + (lane >> 2); if (p0 > 483) p0 = 483;
        int p1 = p0 + 8;                if (p1 > 483) p1 = 483;
        int y0 = p0 / 22, x0 = p0 - y0 * 22;
        int y1 = p1 / 22, x1 = p1 - y1 * 22;
        int dx0 = (lane & 3) * 2;
        c0[i] = (x0 & 1) * PL_U32 + y0 * 16 + ((x0 + dx0 - (x0 & 1)) >> 1);
        c1[i] = (x1 & 1) * PL_U32 + y1 * 16 + ((x1 + dx0 - (x1 & 1)) >> 1);
    }

    float acc[4][4][4];
    #pragma unroll
    for (int i = 0; i < 4; i++)
        #pragma unroll
        for (int n = 0; n < 4; n++)
            { acc[i][n][0]=0.f; acc[i][n][1]=0.f; acc[i][n][2]=0.f; acc[i][n][3]=0.f; }

    const uint4* bfr = (const uint4*)g_Bfrag2;

    #pragma unroll 1
    for (int ic = 0; ic < 15; ic++) {
        #pragma unroll 1
        for (int dyp = 0; dyp < 4; dyp++) {
            const int ks = ic * 4 + dyp;
            uint4 q0 = bfr[(ks * 4 + 0) * 32 + lane];
            uint4 q1 = bfr[(ks * 4 + 1) * 32 + lane];
            uint4 q2 = bfr[(ks * 4 + 2) * 32 + lane];
            uint4 q3 = bfr[(ks * 4 + 3) * 32 + lane];
            const int kb0 = (ic * 29 + dyp * 2) * 16;
            const int kb1 = kb0 + 16;
            #pragma unroll
            for (int i = 0; i < 4; i++) {
                u32 ah0 = pH[c0[i] + kb0], ah1 = pH[c1[i] + kb0];
                u32 ah2 = pH[c0[i] + kb1], ah3 = pH[c1[i] + kb1];
                u32 al0 = pL[c0[i] + kb0], al1 = pL[c1[i] + kb0];
                u32 al2 = pL[c0[i] + kb1], al3 = pL[c1[i] + kb1];
                mma_bf16(acc[i][0], ah0, ah1, ah2, ah3, q0.x, q0.y);
                mma_bf16(acc[i][0], ah0, ah1, ah2, ah3, q0.z, q0.w);
                mma_bf16(acc[i][0], al0, al1, al2, al3, q0.x, q0.y);
                mma_bf16(acc[i][1], ah0, ah1, ah2, ah3, q1.x, q1.y);
                mma_bf16(acc[i][1], ah0, ah1, ah2, ah3, q1.z, q1.w);
                mma_bf16(acc[i][1], al0, al1, al2, al3, q1.x, q1.y);
                mma_bf16(acc[i][2], ah0, ah1, ah2, ah3, q2.x, q2.y);
                mma_bf16(acc[i][2], ah0, ah1, ah2, ah3, q2.z, q2.w);
                mma_bf16(acc[i][2], al0, al1, al2, al3, q2.x, q2.y);
                mma_bf16(acc[i][3], ah0, ah1, ah2, ah3, q3.x, q3.y);
                mma_bf16(acc[i][3], ah0, ah1, ah2, ah3, q3.z, q3.w);
                mma_bf16(acc[i][3], al0, al1, al2, al3, q3.x, q3.y);
            }
        }
    }

    __syncthreads();
    float* stg = (float*)smem;             // [484][33]
    #pragma unroll
    for (int i = 0; i < 4; i++) {
        int mt = w * 4 + i; if (mt > 30) mt = 30;
        int r0 = mt * 16 + (lane >> 2), r1 = r0 + 8;
        #pragma unroll
        for (int n = 0; n < 4; n++) {
            int oc = n * 8 + (lane & 3) * 2;
            if (oc < C2) {
                float s0 = scS[oc], h0 = shS[oc];
                float s1 = scS[oc + 1], h1 = shS[oc + 1];
                if (r0 < 484) {
                    stg[r0 * 33 + oc]     = fmaxf(acc[i][n][0] * s0 + h0, 0.f);
                    stg[r0 * 33 + oc + 1] = fmaxf(acc[i][n][1] * s1 + h1, 0.f);
                }
                if (r1 < 484) {
                    stg[r1 * 33 + oc]     = fmaxf(acc[i][n][2] * s0 + h0, 0.f);
                    stg[r1 * 33 + oc + 1] = fmaxf(acc[i][n][3] * s1 + h1, 0.f);
                }
            }
        }
    }
    __syncthreads();
    // pool -> hi/lo bf16 planes for fc1 (k = oc*121 + pos exactly)
    for (int i = t; i < 3630; i += 256) {
        int oc = i / 121, pos = i % 121;
        int py = pos / 11, px = pos % 11;
        int p00 = (2 * py) * 22 + 2 * px;
        float v = fmaxf(fmaxf(stg[p00 * 33 + oc], stg[(p00 + 1) * 33 + oc]),
                        fmaxf(stg[(p00 + 22) * 33 + oc], stg[(p00 + 23) * 33 + oc]));
        u16 h = bf16_bits(v);
        u16 l = bf16_bits(v - __uint_as_float((u32)h << 16));
        g_p2h[(size_t)b * FC1_IN + i] = h;
        g_p2l[(size_t)b * FC1_IN + i] = l;
    }
}

// ---------------- kernel 3: FC1 via warp mma (bf16, 3-term, K-split 8) ----------------
__global__ __launch_bounds__(256, 1) void fc1_mma_kernel()
{
    const int t = threadIdx.x, w = t >> 5, lane = t & 31;
    const int mt = blockIdx.x;        // 0..15
    const int kz = blockIdx.y;        // 0..7

    const int row0 = mt * 128 + w * 16 + (lane >> 2);
    const size_t base0 = (size_t)row0 * FC1_IN;
    const size_t base1 = (size_t)(row0 + 8) * FC1_IN;
    const int koff = (lane & 3) * 2;

    const int ks0 = kz * 28 + (kz < 3 ? kz : 3);
    const int nks = 28 + (kz < 3 ? 1 : 0);

    float acc[25][4];
    #pragma unroll
    for (int n = 0; n < 25; n++)
        { acc[n][0]=0.f; acc[n][1]=0.f; acc[n][2]=0.f; acc[n][3]=0.f; }

    #pragma unroll 1
    for (int ks = ks0; ks < ks0 + nks; ks++) {
        const int k0 = ks * 16 + koff;
        u32 ah0 = *(const u32*)&g_p2h[base0 + k0];
        u32 ah1 = *(const u32*)&g_p2h[base1 + k0];
        u32 ah2 = *(const u32*)&g_p2h[base0 + k0 + 8];
        u32 ah3 = *(const u32*)&g_p2h[base1 + k0 + 8];
        u32 al0 = *(const u32*)&g_p2l[base0 + k0];
        u32 al1 = *(const u32*)&g_p2l[base1 + k0];
        u32 al2 = *(const u32*)&g_p2l[base0 + k0 + 8];
        u32 al3 = *(const u32*)&g_p2l[base1 + k0 + 8];
        const uint4* bp = &g_W1frag[(size_t)ks * 25 * 32 + lane];
        #pragma unroll
        for (int n = 0; n < 25; n++) {
            uint4 q = bp[n * 32];
            mma_bf16(acc[n], ah0, ah1, ah2, ah3, q.x, q.y);
            mma_bf16(acc[n], ah0, ah1, ah2, ah3, q.z, q.w);
            mma_bf16(acc[n], al0, al1, al2, al3, q.x, q.y);
        }
    }

    float* dst = g_fc1p + (size_t)kz * B * FC1_OUT;
    const int r0 = mt * 128 + w * 16 + (lane >> 2);
    const int r1 = r0 + 8;
    #pragma unroll
    for (int n = 0; n < 25; n++) {
        int o = n * 8 + (lane & 3) * 2;
        dst[(size_t)r0 * FC1_OUT + o]     = acc[n][0];
        dst[(size_t)r0 * FC1_OUT + o + 1] = acc[n][1];
        dst[(size_t)r1 * FC1_OUT + o]     = acc[n][2];
        dst[(size_t)r1 * FC1_OUT + o + 1] = acc[n][3];
    }
}

// ---------------- kernel 4: FC2 + sigmoid ----------------
__global__ __launch_bounds__(256) void fc2_kernel(
    const float* __restrict__ fc1b,
    const float* __restrict__ w2, const float* __restrict__ b2,
    float* __restrict__ out)
{
    const int warp = threadIdx.x >> 5, lane = threadIdx.x & 31;
    const int b = blockIdx.x * 8 + warp;
    const size_t PS = (size_t)B * FC1_OUT;
    const float* base = g_fc1p + (size_t)b * FC1_OUT;
    float s0 = 0.f, s1 = 0.f;
    for (int o = lane; o < FC1_OUT; o += 32) {
        float v = fc1b[o];
        #pragma unroll
        for (int p = 0; p < KSPLIT; p++)
            v += base[p * PS + o];
        v = fmaxf(v, 0.f);
        s0 += v * w2[o];
        s1 += v * w2[FC1_OUT + o];
    }
    #pragma unroll
    for (int d = 16; d > 0; d >>= 1) {
        s0 += __shfl_xor_sync(0xFFFFFFFFu, s0, d);
        s1 += __shfl_xor_sync(0xFFFFFFFFu, s1, d);
    }
    if (lane == 0) {
        out[2 * b + 0] = 1.f / (1.f + expf(-(s0 + b2[0])));
        out[2 * b + 1] = 1.f / (1.f + expf(-(s1 + b2[1])));
    }
}

// ---------------- launch ----------------
extern "C" void kernel_launch(void* const* d_in, const int* in_sizes, int n_in,
                              void* d_out, int out_size)
{
    const float* x       = (const float*)d_in[0];
    const float* log_s   = (const float*)d_in[1];
    const float* log_a   = (const float*)d_in[2];
    const float* log_d   = (const float*)d_in[3];
    const float* log_r   = (const float*)d_in[4];
    const float* conv1_w = (const float*)d_in[5];
    const float* conv1_b = (const float*)d_in[6];
    const float* bn1_g   = (const float*)d_in[7];
    const float* bn1_b   = (const float*)d_in[8];
    const float* bn1_m   = (const float*)d_in[9];
    const float* bn1_v   = (const float*)d_in[10];
    const float* conv2_w = (const float*)d_in[11];
    const float* conv2_b = (const float*)d_in[12];
    const float* bn2_g   = (const float*)d_in[13];
    const float* bn2_b   = (const float*)d_in[14];
    const float* bn2_m   = (const float*)d_in[15];
    const float* bn2_v   = (const float*)d_in[16];
    const float* fc1_w   = (const float*)d_in[17];
    const float* fc1_b   = (const float*)d_in[18];
    const float* fc2_w   = (const float*)d_in[19];
    const float* fc2_b   = (const float*)d_in[20];
    float* out = (float*)d_out;

    static int smem_set = 0;
    if (!smem_set) {
        cudaFuncSetAttribute(conv2_mma_kernel,
                             cudaFuncAttributeMaxDynamicSharedMemorySize, SM_TOT2);
        smem_set = 1;
    }

    prep_b_frag<<<30, 256>>>(conv2_w);
    prep_w1_frag<<<(NKS1 * 25 * 32 + 255) / 256, 256>>>(fc1_w);
    conv1_pcen_kernel<<<B, 288>>>(x, log_s, log_a, log_d, log_r,
                                  conv1_w, conv1_b, bn1_g, bn1_b, bn1_m, bn1_v);
    conv2_mma_kernel<<<B, 256, SM_TOT2>>>(conv2_b, bn2_g, bn2_b, bn2_m, bn2_v);
    fc1_mma_kernel<<<dim3(16, KSPLIT), 256>>>();
    fc2_kernel<<<B / 8, 256>>>(fc1_b, fc2_w, fc2_b, out);
}

// round 9
// speedup vs baseline: 2.6552x; 1.3724x over previous
#include <cuda_runtime.h>
#include <cuda_bf16.h>
#include <math.h>
#include <stdint.h>

#define B 2048
#define C1 15
#define C2 30
#define P1 29
#define P2 11
#define IN2P 32
#define FC1_IN (30*11*11)
#define FC1_OUT 200
#define KSPLIT 8
#define NKS1 227              // ceil(3630/16)

typedef unsigned long long ull;
typedef __nv_bfloat16 bf16;
typedef uint16_t u16;
typedef uint32_t u32;

// ---------------- warp mma m16n8k16 bf16 ----------------
__device__ __forceinline__ void mma_bf16(float* d, u32 a0, u32 a1, u32 a2, u32 a3,
                                         u32 b0, u32 b1) {
    asm volatile(
        "mma.sync.aligned.m16n8k16.row.col.f32.bf16.bf16.f32 "
        "{%0,%1,%2,%3}, {%4,%5,%6,%7}, {%8,%9}, {%0,%1,%2,%3};"
        : "+f"(d[0]), "+f"(d[1]), "+f"(d[2]), "+f"(d[3])
        : "r"(a0), "r"(a1), "r"(a2), "r"(a3), "r"(b0), "r"(b1));
}

__device__ __forceinline__ u16 bf16_bits(float v) {
    return __bfloat16_as_ushort(__float2bfloat16(v));
}

// ---------------- scratch ----------------
__device__ float g_p1[B * C1 * P1 * IN2P];
__device__ float g_fc1p[KSPLIT * B * FC1_OUT];
__device__ __align__(16) u32 g_Bfrag2[60 * 4 * 32 * 4];      // conv2 B frags
__device__ __align__(16) uint4 g_B1frag[2 * 4 * 32];          // conv1 B frags
__device__ __align__(16) uint4 g_W1frag[NKS1 * 25 * 32];      // fc1 W frags
__device__ __align__(4) u16 g_p2h[B * FC1_IN + 64];
__device__ __align__(4) u16 g_p2l[B * FC1_IN + 64];

// ---------------- kernel 0a: prep conv2 B fragments ----------------
__global__ void prep_b_frag(const float* __restrict__ w2)
{
    int idx = blockIdx.x * 256 + threadIdx.x;
    if (idx >= 7680) return;
    int lane = idx & 31, nt = (idx >> 5) & 3, ks = idx >> 7;
    int ic = ks >> 2, dyp = ks & 3;
    int oc = nt * 8 + (lane >> 2), k0 = (lane & 3) * 2;
    int dy0 = dyp * 2, dy1 = dy0 + 1;

    float v[4] = {0.f, 0.f, 0.f, 0.f};
    if (oc < C2) {
        const float* wb = w2 + (oc * C1 + ic) * 49;
        v[0] = wb[dy0 * 7 + k0];
        if (k0 + 1 < 7) v[1] = wb[dy0 * 7 + k0 + 1];
        if (dy1 < 7) {
            v[2] = wb[dy1 * 7 + k0];
            if (k0 + 1 < 7) v[3] = wb[dy1 * 7 + k0 + 1];
        }
    }
    u16 h[4], l[4];
    #pragma unroll
    for (int i = 0; i < 4; i++) {
        h[i] = bf16_bits(v[i]);
        l[i] = bf16_bits(v[i] - __uint_as_float((u32)h[i] << 16));
    }
    uint4 q;
    q.x = (u32)h[0] | ((u32)h[1] << 16);
    q.y = (u32)h[2] | ((u32)h[3] << 16);
    q.z = (u32)l[0] | ((u32)l[1] << 16);
    q.w = (u32)l[2] | ((u32)l[3] << 16);
    ((uint4*)g_Bfrag2)[idx] = q;
}

// ---------------- kernel 0b: prep conv1 B fragments (2 nt x 4 ks x 32) ----------------
__global__ void prep_b1_frag(const float* __restrict__ w1)
{
    int idx = threadIdx.x;               // 256 threads
    int lane = idx & 31, ks = (idx >> 5) & 3, nt = idx >> 7;
    int oc = nt * 8 + (lane >> 2), k0 = (lane & 3) * 2;
    int dy0 = ks * 2, dy1 = dy0 + 1;

    float v[4] = {0.f, 0.f, 0.f, 0.f};
    if (oc < C1) {
        const float* wb = w1 + oc * 49;
        if (dy0 < 7) {
            v[0] = wb[dy0 * 7 + k0];
            if (k0 + 1 < 7) v[1] = wb[dy0 * 7 + k0 + 1];
        }
        if (dy1 < 7) {
            v[2] = wb[dy1 * 7 + k0];
            if (k0 + 1 < 7) v[3] = wb[dy1 * 7 + k0 + 1];
        }
    }
    u16 h[4], l[4];
    #pragma unroll
    for (int i = 0; i < 4; i++) {
        h[i] = bf16_bits(v[i]);
        l[i] = bf16_bits(v[i] - __uint_as_float((u32)h[i] << 16));
    }
    uint4 q;
    q.x = (u32)h[0] | ((u32)h[1] << 16);
    q.y = (u32)h[2] | ((u32)h[3] << 16);
    q.z = (u32)l[0] | ((u32)l[1] << 16);
    q.w = (u32)l[2] | ((u32)l[3] << 16);
    g_B1frag[(nt * 4 + ks) * 32 + lane] = q;
}

// ---------------- kernel 0c: prep fc1 W fragments ----------------
__global__ void prep_w1_frag(const float* __restrict__ w)
{
    int idx = blockIdx.x * 256 + threadIdx.x;
    if (idx >= NKS1 * 25 * 32) return;
    int lane = idx & 31;
    int nt = (idx >> 5) % 25;
    int ks = idx / (25 * 32);
    int o = nt * 8 + (lane >> 2);
    int k0 = ks * 16 + (lane & 3) * 2;
    const float* wr = w + (size_t)o * FC1_IN;

    float v[4];
    v[0] = (k0     < FC1_IN) ? wr[k0]     : 0.f;
    v[1] = (k0 + 1 < FC1_IN) ? wr[k0 + 1] : 0.f;
    v[2] = (k0 + 8 < FC1_IN) ? wr[k0 + 8] : 0.f;
    v[3] = (k0 + 9 < FC1_IN) ? wr[k0 + 9] : 0.f;
    u16 h[4], l[4];
    #pragma unroll
    for (int i = 0; i < 4; i++) {
        h[i] = bf16_bits(v[i]);
        l[i] = bf16_bits(v[i] - __uint_as_float((u32)h[i] << 16));
    }
    uint4 q;
    q.x = (u32)h[0] | ((u32)h[1] << 16);
    q.y = (u32)h[2] | ((u32)h[3] << 16);
    q.z = (u32)l[0] | ((u32)l[1] << 16);
    q.w = (u32)l[2] | ((u32)l[3] << 16);
    g_W1frag[idx] = q;
}

// ---------------- kernel 1: PCEN + conv1 via warp mma + BN + ReLU + pool ----------------
// smem: fp32 img [64*65] | hi-even | hi-odd | lo-even | lo-odd (u16 x 4096 each) | BN
#define SM1_IMG 0
#define SM1_HE  16640
#define SM1_LE  33024
#define SM1_SC  49408
#define SM1_SH  49472
#define SM1_TOT 50816           // padded for harmless OOB reads of zero-weight taps
#define PL1 2048                // u32 per plane parity copy

__global__ __launch_bounds__(256) void conv1_pcen_kernel(
    const float* __restrict__ x,
    const float* __restrict__ log_s, const float* __restrict__ log_alpha,
    const float* __restrict__ log_delta, const float* __restrict__ log_r,
    const float* __restrict__ b1,
    const float* __restrict__ g,  const float* __restrict__ be,
    const float* __restrict__ mu, const float* __restrict__ va)
{
    extern __shared__ __align__(16) char smem[];
    float* img = (float*)(smem + SM1_IMG);
    u16* hE16 = (u16*)(smem + SM1_HE);
    u16* lE16 = (u16*)(smem + SM1_LE);
    const u32* pH = (const u32*)(smem + SM1_HE);
    const u32* pL = (const u32*)(smem + SM1_LE);
    float* scS = (float*)(smem + SM1_SC);
    float* shS = (float*)(smem + SM1_SH);

    const int b = blockIdx.x, t = threadIdx.x;
    const int w = t >> 5, lane = t & 31;
    const float* xb = x + (size_t)b * 4096;

    for (int i = t; i < 4096; i += 256)
        img[(i >> 6) * 65 + (i & 63)] = xb[i];
    if (t < 16) {
        if (t < C1) {
            float inv = g[t] * rsqrtf(va[t] + 1e-5f);
            scS[t] = inv;
            shS[t] = (b1[t] - mu[t]) * inv + be[t];
        } else { scS[t] = 0.f; shS[t] = 0.f; }
    }
    // per-warp conv1 B fragments
    uint4 qf[2][4];
    #pragma unroll
    for (int nt = 0; nt < 2; nt++)
        #pragma unroll
        for (int ks = 0; ks < 4; ks++)
            qf[nt][ks] = g_B1frag[(nt * 4 + ks) * 32 + lane];
    __syncthreads();

    // PCEN recurrence (thread t<64 owns row t)
    if (t < 64) {
        const float s     = expf(log_s[0]);
        const float alpha = expf(log_alpha[0]);
        const float delta = expf(log_delta[0]);
        const float r     = expf(log_r[0]);
        const float oms   = 1.0f - s;
        const float dr    = powf(delta, r);
        float* row = img + t * 65;
        float m = 0.0f;
        #pragma unroll 4
        for (int ww = 0; ww < 64; ww++) {
            float xv = row[ww];
            m = (ww == 0) ? s * xv : oms * m + s * xv;
            float Ma = __powf(m + 1e-6f, alpha);
            row[ww] = __powf(__fdividef(xv, Ma) + delta, r) - dr;
        }
    }
    __syncthreads();

    // plane build: hi/lo bf16, even + odd parity copies
    {
        u16* hO16 = hE16 + 4096;
        u16* lO16 = lE16 + 4096;
        for (int i = t; i < 4096; i += 256) {
            float v = img[(i >> 6) * 65 + (i & 63)];
            u16 h = bf16_bits(v);
            u16 l = bf16_bits(v - __uint_as_float((u32)h << 16));
            hE16[i] = h; lE16[i] = l;
            if (i > 0) { hO16[i - 1] = h; lO16[i - 1] = l; }
        }
        if (t == 0) { hO16[4095] = 0; lO16[4095] = 0; }
    }
    __syncthreads();

    const int r = lane >> 2;
    const int koff = (lane & 3) * 2;

    // m-tiles: 29 y-pairs x 8 x-octets = 232; tile = 2 rows x 8 cols
    for (int mt = w; mt < 232; mt += 8) {
        const int py = mt >> 3, xo = mt & 7;
        const int y0 = 2 * py, x0 = xo * 8;
        const int xbase = x0 + r + koff;

        float acc[2][4];
        #pragma unroll
        for (int nt = 0; nt < 2; nt++)
            { acc[nt][0]=0.f; acc[nt][1]=0.f; acc[nt][2]=0.f; acc[nt][3]=0.f; }

        #pragma unroll
        for (int ks = 0; ks < 4; ks++) {
            const int eA = (y0 + 2 * ks) * 64 + xbase;
            const int i0 = ((eA & 1) << 11) + (eA >> 1);
            u32 hA = pH[i0], hB = pH[i0 + 32], hC = pH[i0 + 64];
            u32 lA = pL[i0], lB = pL[i0 + 32], lC = pL[i0 + 64];
            #pragma unroll
            for (int nt = 0; nt < 2; nt++) {
                uint4 q = qf[nt][ks];
                mma_bf16(acc[nt], hA, hB, hB, hC, q.x, q.y);
                mma_bf16(acc[nt], hA, hB, hB, hC, q.z, q.w);
                mma_bf16(acc[nt], lA, lB, lB, lC, q.x, q.y);
            }
        }

        // BN + ReLU + 2x2 pool (vertical in-thread, horizontal via shfl)
        #pragma unroll
        for (int nt = 0; nt < 2; nt++) {
            int oc = nt * 8 + (lane & 3) * 2;
            float s0 = scS[oc], h0 = shS[oc];
            float s1 = scS[oc + 1], h1 = shS[oc + 1];
            float m0 = fmaxf(fmaxf(acc[nt][0] * s0 + h0, 0.f),
                             fmaxf(acc[nt][2] * s0 + h0, 0.f));
            float m1 = fmaxf(fmaxf(acc[nt][1] * s1 + h1, 0.f),
                             fmaxf(acc[nt][3] * s1 + h1, 0.f));
            m0 = fmaxf(m0, __shfl_xor_sync(0xFFFFFFFFu, m0, 4));
            m1 = fmaxf(m1, __shfl_xor_sync(0xFFFFFFFFu, m1, 4));
            if (!(r & 1)) {
                int px = (x0 + r) >> 1;
                if (px < P1) {
                    float* ob = g_p1 + (size_t)b * (C1 * P1 * IN2P) + py * IN2P + px;
                    if (oc < C1)     ob[oc * (P1 * IN2P)] = m0;
                    if (oc + 1 < C1) ob[(oc + 1) * (P1 * IN2P)] = m1;
                }
            }
        }
    }
}

// ---------------- kernel 2: conv2 via warp mma (bf16 k16, 3-term split) ----------------
#define PL_U32 6960
#define SM_PHE 0
#define SM_PLE 55680
#define SM_SC  111360
#define SM_SH  111488
#define SM_TOT2 111616

__global__ __launch_bounds__(256, 2) void conv2_mma_kernel(
    const float* __restrict__ b2,
    const float* __restrict__ g,  const float* __restrict__ be,
    const float* __restrict__ mu, const float* __restrict__ va)
{
    extern __shared__ __align__(16) char smem[];
    u16* hE16 = (u16*)(smem + SM_PHE);
    u16* lE16 = (u16*)(smem + SM_PLE);
    const u32* pH = (const u32*)(smem + SM_PHE);
    const u32* pL = (const u32*)(smem + SM_PLE);
    float* scS = (float*)(smem + SM_SC);
    float* shS = (float*)(smem + SM_SH);

    const int t = threadIdx.x, w = t >> 5, lane = t & 31;
    const int b = blockIdx.x;

    {
        const float* src = g_p1 + (size_t)b * 13920;
        u16* hO16 = hE16 + 13920;
        u16* lO16 = lE16 + 13920;
        for (int i = t; i < 13920; i += 256) {
            float v = src[i];
            u16 h = bf16_bits(v);
            u16 l = bf16_bits(v - __uint_as_float((u32)h << 16));
            hE16[i] = h; lE16[i] = l;
            if (i > 0) { hO16[i - 1] = h; lO16[i - 1] = l; }
        }
        if (t == 0) { hO16[13919] = 0; lO16[13919] = 0; }
    }
    if (t < C2) {
        float inv = g[t] * rsqrtf(va[t] + 1e-5f);
        scS[t] = inv;
        shS[t] = (b2[t] - mu[t]) * inv + be[t];
    }
    __syncthreads();

    int c0[4], c1[4];
    #pragma unroll
    for (int i = 0; i < 4; i++) {
        int mt = w * 4 + i; if (mt > 30) mt = 30;
        int p0 = mt * 16 + (lane >> 2); if (p0 > 483) p0 = 483;
        int p1 = p0 + 8;                if (p1 > 483) p1 = 483;
        int y0 = p0 / 22, x0 = p0 - y0 * 22;
        int y1 = p1 / 22, x1 = p1 - y1 * 22;
        int dx0 = (lane & 3) * 2;
        c0[i] = (x0 & 1) * PL_U32 + y0 * 16 + ((x0 + dx0 - (x0 & 1)) >> 1);
        c1[i] = (x1 & 1) * PL_U32 + y1 * 16 + ((x1 + dx0 - (x1 & 1)) >> 1);
    }

    float acc[4][4][4];
    #pragma unroll
    for (int i = 0; i < 4; i++)
        #pragma unroll
        for (int n = 0; n < 4; n++)
            { acc[i][n][0]=0.f; acc[i][n][1]=0.f; acc[i][n][2]=0.f; acc[i][n][3]=0.f; }

    const uint4* bfr = (const uint4*)g_Bfrag2;

    #pragma unroll 1
    for (int ic = 0; ic < 15; ic++) {
        #pragma unroll 1
        for (int dyp = 0; dyp < 4; dyp++) {
            const int ks = ic * 4 + dyp;
            uint4 q0 = bfr[(ks * 4 + 0) * 32 + lane];
            uint4 q1 = bfr[(ks * 4 + 1) * 32 + lane];
            uint4 q2 = bfr[(ks * 4 + 2) * 32 + lane];
            uint4 q3 = bfr[(ks * 4 + 3) * 32 + lane];
            const int kb0 = (ic * 29 + dyp * 2) * 16;
            const int kb1 = kb0 + 16;
            #pragma unroll
            for (int i = 0; i < 4; i++) {
                u32 ah0 = pH[c0[i] + kb0], ah1 = pH[c1[i] + kb0];
                u32 ah2 = pH[c0[i] + kb1], ah3 = pH[c1[i] + kb1];
                u32 al0 = pL[c0[i] + kb0], al1 = pL[c1[i] + kb0];
                u32 al2 = pL[c0[i] + kb1], al3 = pL[c1[i] + kb1];
                mma_bf16(acc[i][0], ah0, ah1, ah2, ah3, q0.x, q0.y);
                mma_bf16(acc[i][0], ah0, ah1, ah2, ah3, q0.z, q0.w);
                mma_bf16(acc[i][0], al0, al1, al2, al3, q0.x, q0.y);
                mma_bf16(acc[i][1], ah0, ah1, ah2, ah3, q1.x, q1.y);
                mma_bf16(acc[i][1], ah0, ah1, ah2, ah3, q1.z, q1.w);
                mma_bf16(acc[i][1], al0, al1, al2, al3, q1.x, q1.y);
                mma_bf16(acc[i][2], ah0, ah1, ah2, ah3, q2.x, q2.y);
                mma_bf16(acc[i][2], ah0, ah1, ah2, ah3, q2.z, q2.w);
                mma_bf16(acc[i][2], al0, al1, al2, al3, q2.x, q2.y);
                mma_bf16(acc[i][3], ah0, ah1, ah2, ah3, q3.x, q3.y);
                mma_bf16(acc[i][3], ah0, ah1, ah2, ah3, q3.z, q3.w);
                mma_bf16(acc[i][3], al0, al1, al2, al3, q3.x, q3.y);
            }
        }
    }

    __syncthreads();
    float* stg = (float*)smem;             // [484][33]
    #pragma unroll
    for (int i = 0; i < 4; i++) {
        int mt = w * 4 + i; if (mt > 30) mt = 30;
        int r0 = mt * 16 + (lane >> 2), r1 = r0 + 8;
        #pragma unroll
        for (int n = 0; n < 4; n++) {
            int oc = n * 8 + (lane & 3) * 2;
            if (oc < C2) {
                float s0 = scS[oc], h0 = shS[oc];
                float s1 = scS[oc + 1], h1 = shS[oc + 1];
                if (r0 < 484) {
                    stg[r0 * 33 + oc]     = fmaxf(acc[i][n][0] * s0 + h0, 0.f);
                    stg[r0 * 33 + oc + 1] = fmaxf(acc[i][n][1] * s1 + h1, 0.f);
                }
                if (r1 < 484) {
                    stg[r1 * 33 + oc]     = fmaxf(acc[i][n][2] * s0 + h0, 0.f);
                    stg[r1 * 33 + oc + 1] = fmaxf(acc[i][n][3] * s1 + h1, 0.f);
                }
            }
        }
    }
    __syncthreads();
    for (int i = t; i < 3630; i += 256) {
        int oc = i / 121, pos = i % 121;
        int py = pos / 11, px = pos % 11;
        int p00 = (2 * py) * 22 + 2 * px;
        float v = fmaxf(fmaxf(stg[p00 * 33 + oc], stg[(p00 + 1) * 33 + oc]),
                        fmaxf(stg[(p00 + 22) * 33 + oc], stg[(p00 + 23) * 33 + oc]));
        u16 h = bf16_bits(v);
        u16 l = bf16_bits(v - __uint_as_float((u32)h << 16));
        g_p2h[(size_t)b * FC1_IN + i] = h;
        g_p2l[(size_t)b * FC1_IN + i] = l;
    }
}

// ---------------- kernel 3: FC1 via warp mma (bf16, 3-term, K-split 8) ----------------
__global__ __launch_bounds__(256, 1) void fc1_mma_kernel()
{
    const int t = threadIdx.x, w = t >> 5, lane = t & 31;
    const int mt = blockIdx.x;
    const int kz = blockIdx.y;

    const int row0 = mt * 128 + w * 16 + (lane >> 2);
    const size_t base0 = (size_t)row0 * FC1_IN;
    const size_t base1 = (size_t)(row0 + 8) * FC1_IN;
    const int koff = (lane & 3) * 2;

    const int ks0 = kz * 28 + (kz < 3 ? kz : 3);
    const int nks = 28 + (kz < 3 ? 1 : 0);

    float acc[25][4];
    #pragma unroll
    for (int n = 0; n < 25; n++)
        { acc[n][0]=0.f; acc[n][1]=0.f; acc[n][2]=0.f; acc[n][3]=0.f; }

    #pragma unroll 1
    for (int ks = ks0; ks < ks0 + nks; ks++) {
        const int k0 = ks * 16 + koff;
        u32 ah0 = *(const u32*)&g_p2h[base0 + k0];
        u32 ah1 = *(const u32*)&g_p2h[base1 + k0];
        u32 ah2 = *(const u32*)&g_p2h[base0 + k0 + 8];
        u32 ah3 = *(const u32*)&g_p2h[base1 + k0 + 8];
        u32 al0 = *(const u32*)&g_p2l[base0 + k0];
        u32 al1 = *(const u32*)&g_p2l[base1 + k0];
        u32 al2 = *(const u32*)&g_p2l[base0 + k0 + 8];
        u32 al3 = *(const u32*)&g_p2l[base1 + k0 + 8];
        const uint4* bp = &g_W1frag[(size_t)ks * 25 * 32 + lane];
        #pragma unroll
        for (int n = 0; n < 25; n++) {
            uint4 q = bp[n * 32];
            mma_bf16(acc[n], ah0, ah1, ah2, ah3, q.x, q.y);
            mma_bf16(acc[n], ah0, ah1, ah2, ah3, q.z, q.w);
            mma_bf16(acc[n], al0, al1, al2, al3, q.x, q.y);
        }
    }

    float* dst = g_fc1p + (size_t)kz * B * FC1_OUT;
    const int r0 = mt * 128 + w * 16 + (lane >> 2);
    const int r1 = r0 + 8;
    #pragma unroll
    for (int n = 0; n < 25; n++) {
        int o = n * 8 + (lane & 3) * 2;
        dst[(size_t)r0 * FC1_OUT + o]     = acc[n][0];
        dst[(size_t)r0 * FC1_OUT + o + 1] = acc[n][1];
        dst[(size_t)r1 * FC1_OUT + o]     = acc[n][2];
        dst[(size_t)r1 * FC1_OUT + o + 1] = acc[n][3];
    }
}

// ---------------- kernel 4: FC2 + sigmoid ----------------
__global__ __launch_bounds__(256) void fc2_kernel(
    const float* __restrict__ fc1b,
    const float* __restrict__ w2, const float* __restrict__ b2,
    float* __restrict__ out)
{
    const int warp = threadIdx.x >> 5, lane = threadIdx.x & 31;
    const int b = blockIdx.x * 8 + warp;
    const size_t PS = (size_t)B * FC1_OUT;
    const float* base = g_fc1p + (size_t)b * FC1_OUT;
    float s0 = 0.f, s1 = 0.f;
    for (int o = lane; o < FC1_OUT; o += 32) {
        float v = fc1b[o];
        #pragma unroll
        for (int p = 0; p < KSPLIT; p++)
            v += base[p * PS + o];
        v = fmaxf(v, 0.f);
        s0 += v * w2[o];
        s1 += v * w2[FC1_OUT + o];
    }
    #pragma unroll
    for (int d = 16; d > 0; d >>= 1) {
        s0 += __shfl_xor_sync(0xFFFFFFFFu, s0, d);
        s1 += __shfl_xor_sync(0xFFFFFFFFu, s1, d);
    }
    if (lane == 0) {
        out[2 * b + 0] = 1.f / (1.f + expf(-(s0 + b2[0])));
        out[2 * b + 1] = 1.f / (1.f + expf(-(s1 + b2[1])));
    }
}

// ---------------- launch ----------------
extern "C" void kernel_launch(void* const* d_in, const int* in_sizes, int n_in,
                              void* d_out, int out_size)
{
    const float* x       = (const float*)d_in[0];
    const float* log_s   = (const float*)d_in[1];
    const float* log_a   = (const float*)d_in[2];
    const float* log_d   = (const float*)d_in[3];
    const float* log_r   = (const float*)d_in[4];
    const float* conv1_w = (const float*)d_in[5];
    const float* conv1_b = (const float*)d_in[6];
    const float* bn1_g   = (const float*)d_in[7];
    const float* bn1_b   = (const float*)d_in[8];
    const float* bn1_m   = (const float*)d_in[9];
    const float* bn1_v   = (const float*)d_in[10];
    const float* conv2_w = (const float*)d_in[11];
    const float* conv2_b = (const float*)d_in[12];
    const float* bn2_g   = (const float*)d_in[13];
    const float* bn2_b   = (const float*)d_in[14];
    const float* bn2_m   = (const float*)d_in[15];
    const float* bn2_v   = (const float*)d_in[16];
    const float* fc1_w   = (const float*)d_in[17];
    const float* fc1_b   = (const float*)d_in[18];
    const float* fc2_w   = (const float*)d_in[19];
    const float* fc2_b   = (const float*)d_in[20];
    float* out = (float*)d_out;

    static int smem_set = 0;
    if (!smem_set) {
        cudaFuncSetAttribute(conv2_mma_kernel,
                             cudaFuncAttributeMaxDynamicSharedMemorySize, SM_TOT2);
        cudaFuncSetAttribute(conv1_pcen_kernel,
                             cudaFuncAttributeMaxDynamicSharedMemorySize, SM1_TOT);
        smem_set = 1;
    }

    prep_b_frag<<<30, 256>>>(conv2_w);
    prep_b1_frag<<<1, 256>>>(conv1_w);
    prep_w1_frag<<<(NKS1 * 25 * 32 + 255) / 256, 256>>>(fc1_w);
    conv1_pcen_kernel<<<B, 256, SM1_TOT>>>(x, log_s, log_a, log_d, log_r,
                                           conv1_b, bn1_g, bn1_b, bn1_m, bn1_v);
    conv2_mma_kernel<<<B, 256, SM_TOT2>>>(conv2_b, bn2_g, bn2_b, bn2_m, bn2_v);
    fc1_mma_kernel<<<dim3(16, KSPLIT), 256>>>();
    fc2_kernel<<<B / 8, 256>>>(fc1_b, fc2_w, fc2_b, out);
}